// round 15
// baseline (speedup 1.0000x reference)
#include <cuda_runtime.h>
#include <cuda_fp16.h>
#include <math.h>
#include <stdint.h>

#define NSEQ 2048
#define BATCH 2
#define HEADS 8
#define DH 64
#define KRET 32
#define DIM 512
#define NT 32
#define L2E 1.4426950408889634f

__device__ float g_q[(size_t)BATCH * HEADS * NSEQ * DH];
__device__ uint2 g_kf[(size_t)BATCH * NT * 1024];
__device__ uint2 g_vf[(size_t)BATCH * NT * 1024];
__device__ uint32_t g_xf[(size_t)256 * 32 * 32 * 8];
__device__ uint32_t g_af[(size_t)256 * 32 * 32 * 8];
__device__ uint32_t g_wqf[(size_t)64 * 32 * 32 * 4];
__device__ uint32_t g_wkvf[(size_t)16 * 32 * 32 * 4];
__device__ uint32_t g_woutf[(size_t)64 * 32 * 32 * 2];

__device__ __forceinline__ void mma16(float* d, uint32_t a0, uint32_t a1, uint32_t a2,
                                      uint32_t a3, uint32_t b0, uint32_t b1) {
    asm volatile("mma.sync.aligned.m16n8k16.row.col.f32.f16.f16.f32 "
        "{%0,%1,%2,%3}, {%4,%5,%6,%7}, {%8,%9}, {%0,%1,%2,%3};"
        : "+f"(d[0]), "+f"(d[1]), "+f"(d[2]), "+f"(d[3])
        : "r"(a0), "r"(a1), "r"(a2), "r"(a3), "r"(b0), "r"(b1));
}
__device__ __forceinline__ float ex2(float x) {
    float r; asm("ex2.approx.f32 %0, %1;" : "=f"(r) : "f"(x)); return r;
}
__device__ __forceinline__ uint32_t h2bits(__half2 h) {
    uint32_t u; *(__half2*)&u = h; return u;
}
__device__ __forceinline__ uint32_t split_pair_h(float a, float b, uint32_t& lo) {
    __half ha = __float2half_rn(a), hb = __float2half_rn(b);
    float ra = a - __half2float(ha), rb = b - __half2float(hb);
    lo = h2bits(__floats2half2_rn(ra, rb));
    return h2bits(__halves2half2(ha, hb));
}
__device__ __forceinline__ uint32_t s2u(const void* p) {
    return (uint32_t)__cvta_generic_to_shared(p);
}
__device__ __forceinline__ void cpa16(uint32_t s, const void* g) {
    asm volatile("cp.async.cg.shared.global [%0], [%1], 16;" :: "r"(s), "l"(g) : "memory");
}

// ---------------------------------------------------------------------------
__global__ __launch_bounds__(256) void pack_in(const float* __restrict__ x,
                                               const float* __restrict__ Wq,
                                               const float* __restrict__ Wkv,
                                               const float* __restrict__ Wout)
{
    int bx = blockIdx.x;
    if (bx < 1024) {
        int s = bx * 256 + threadIdx.x;
        int band = s >> 10, rem = s & 1023;
        int kfg = rem >> 5, ln = rem & 31;
        int gid = ln >> 2, tig = ln & 3;
        const float* base = x + (size_t)(band * 16 + gid) * DIM + kfg * 16 + 2 * tig;
        float2 x00 = *(const float2*)base;
        float2 x10 = *(const float2*)(base + 8 * DIM);
        float2 x01 = *(const float2*)(base + 8);
        float2 x11 = *(const float2*)(base + 8 * DIM + 8);
        uint32_t l0, l1, l2, l3;
        uint32_t h0 = split_pair_h(x00.x, x00.y, l0);
        uint32_t h1 = split_pair_h(x10.x, x10.y, l1);
        uint32_t h2 = split_pair_h(x01.x, x01.y, l2);
        uint32_t h3 = split_pair_h(x11.x, x11.y, l3);
        *(uint4*)&g_xf[(size_t)s * 8]     = make_uint4(h0, h1, h2, h3);
        *(uint4*)&g_xf[(size_t)s * 8 + 4] = make_uint4(l0, l1, l2, l3);
    } else {
        int sel = (bx - 1024) >> 8;
        const float* W = sel == 0 ? Wq : (sel == 1 ? Wkv : Wout);
        int N = (sel == 1) ? 128 : 512;
        int s = ((bx - 1024) & 255) * 256 + threadIdx.x;
        if (s >= (N / 8) * 1024) return;
        int nfg = s >> 10, rem = s & 1023;
        int kfg = rem >> 5, ln = rem & 31;
        int gid = ln >> 2, tig = ln & 3;
        int n = nfg * 8 + gid, k0 = kfg * 16 + 2 * tig;
        uint32_t bl0, bl1;
        uint32_t bh0 = split_pair_h(W[(size_t)k0 * N + n], W[(size_t)(k0 + 1) * N + n], bl0);
        uint32_t bh1 = split_pair_h(W[(size_t)(k0 + 8) * N + n], W[(size_t)(k0 + 9) * N + n], bl1);
        if (sel == 2) {
            *(uint2*)&g_woutf[(size_t)s * 2] = make_uint2(bh0, bh1);
        } else {
            uint32_t* out = sel == 0 ? g_wqf : g_wkvf;
            *(uint4*)&out[(size_t)s * 4] = make_uint4(bh0, bh1, bl0, bl1);
        }
    }
}

// ---------------------------------------------------------------------------
template <int NF, int SPLITB>
__device__ __forceinline__ void gemm_core_t(const uint32_t* __restrict__ APK,
                                            const uint32_t* __restrict__ BPK,
                                            int band0, int nf0, int KFG,
                                            uint32_t* AF, uint32_t* BF,
                                            float S[][4])
{
    const int tid = threadIdx.x, lane = tid & 31, w = tid >> 5;
    const int mw = w & 3, nh = w >> 2;
    const int nslab = KFG >> 1;
    const int BSTG = NF * (SPLITB ? 256 : 128);
    const int BITER = SPLITB ? NF / 4 : NF / 8;
    const uint32_t a_su[2] = {s2u(AF), s2u(AF + 2048)};
    const uint32_t b_su[2] = {s2u(BF), s2u(BF + BSTG)};

    #pragma unroll
    for (int r = 0; r < NF / 2; r++)
        #pragma unroll
        for (int c = 0; c < 4; c++) S[r][c] = 0.f;

    #pragma unroll
    for (int it = 0; it < 2; it++) {
        int idx = tid + it * 256;
        int kf2 = idx >> 8, mb = (idx >> 6) & 3, ln = (idx >> 1) & 31, hf = idx & 1;
        cpa16(a_su[0] + (((kf2 * 4 + mb) * 32 + ln) * 8 + hf * 4) * 4,
              APK + ((size_t)((band0 + mb) * KFG + kf2) * 32 + ln) * 8 + hf * 4);
    }
    #pragma unroll
    for (int it = 0; it < BITER; it++) {
        int idx = tid + it * 256;
        if (SPLITB) {
            int kf2 = idx / (32 * NF), nf = (idx >> 5) % NF, lnb = idx & 31;
            cpa16(b_su[0] + ((kf2 * NF + nf) * 32 + lnb) * 16,
                  BPK + ((size_t)((nf0 + nf) * KFG + kf2) * 32 + lnb) * 4);
        } else {
            int kf2 = idx / (NF * 16), rem = idx % (NF * 16);
            int nf = rem >> 4, cq = rem & 15;
            cpa16(b_su[0] + ((kf2 * NF + nf) * 64 + cq * 4) * 4,
                  BPK + ((size_t)(nf0 + nf) * KFG + kf2) * 64 + cq * 4);
        }
    }
    asm volatile("cp.async.commit_group;" ::: "memory");

    for (int ks = 0; ks < nslab; ks++) {
        const int cur = ks & 1;
        __syncthreads();
        if (ks + 1 < nslab) {
            const int st = cur ^ 1;
            #pragma unroll
            for (int it = 0; it < 2; it++) {
                int idx = tid + it * 256;
                int kf2 = idx >> 8, mb = (idx >> 6) & 3, ln = (idx >> 1) & 31, hf = idx & 1;
                int kfg = (ks + 1) * 2 + kf2;
                cpa16(a_su[st] + (((kf2 * 4 + mb) * 32 + ln) * 8 + hf * 4) * 4,
                      APK + ((size_t)((band0 + mb) * KFG + kfg) * 32 + ln) * 8 + hf * 4);
            }
            #pragma unroll
            for (int it = 0; it < BITER; it++) {
                int idx = tid + it * 256;
                if (SPLITB) {
                    int kf2 = idx / (32 * NF), nf = (idx >> 5) % NF, lnb = idx & 31;
                    int kfg = (ks + 1) * 2 + kf2;
                    cpa16(b_su[st] + ((kf2 * NF + nf) * 32 + lnb) * 16,
                          BPK + ((size_t)((nf0 + nf) * KFG + kfg) * 32 + lnb) * 4);
                } else {
                    int kf2 = idx / (NF * 16), rem = idx % (NF * 16);
                    int nf = rem >> 4, cq = rem & 15;
                    int kfg = (ks + 1) * 2 + kf2;
                    cpa16(b_su[st] + ((kf2 * NF + nf) * 64 + cq * 4) * 4,
                          BPK + ((size_t)(nf0 + nf) * KFG + kfg) * 64 + cq * 4);
                }
            }
        }
        asm volatile("cp.async.commit_group;" ::: "memory");
        asm volatile("cp.async.wait_group 1;" ::: "memory");
        __syncthreads();

        uint32_t* AFc = AF + cur * 2048;
        uint32_t* BFc = BF + cur * BSTG;
        #pragma unroll
        for (int kf2 = 0; kf2 < 2; kf2++) {
            const uint32_t* ap = &AFc[((kf2 * 4 + mw) * 32 + lane) * 8];
            uint4 ah = *(const uint4*)ap;
            uint4 al = *(const uint4*)(ap + 4);
            #pragma unroll
            for (int nf = 0; nf < NF / 2; nf++) {
                if (SPLITB) {
                    uint4 kb = *(const uint4*)&BFc[((kf2 * NF + nh * (NF / 2) + nf) * 32 + lane) * 4];
                    mma16(S[nf], ah.x, ah.y, ah.z, ah.w, kb.x, kb.y);
                    mma16(S[nf], al.x, al.y, al.z, al.w, kb.x, kb.y);
                    mma16(S[nf], ah.x, ah.y, ah.z, ah.w, kb.z, kb.w);
                } else {
                    uint2 kb = *(const uint2*)&BFc[((kf2 * NF + nh * (NF / 2) + nf) * 32 + lane) * 2];
                    mma16(S[nf], ah.x, ah.y, ah.z, ah.w, kb.x, kb.y);
                    mma16(S[nf], al.x, al.y, al.z, al.w, kb.x, kb.y);
                }
            }
        }
    }
}

// ---------------------------------------------------------------------------
__global__ __launch_bounds__(256) void gemm_qkv()
{
    __shared__ uint32_t AF[2 * 2048];
    __shared__ uint32_t BF[2 * 4096];
    float* vsm   = (float*)BF;
    float* ssbuf = (float*)AF;

    const int tid = threadIdx.x, lane = tid & 31, w = tid >> 5;
    const int mw = w & 3, nh = w >> 2;
    const int gid = lane >> 2, tig = lane & 3;
    const int r0 = blockIdx.y * 64;
    const int bx = blockIdx.x;

    float S[8][4];

    if (bx < 4) {
        gemm_core_t<16, 1>(g_xf, g_wqf, r0 >> 4, bx * 16, DIM >> 4, AF, BF, S);
        #pragma unroll
        for (int rr = 0; rr < 2; rr++) {
            float ss = 0.f;
            #pragma unroll
            for (int nf = 0; nf < 8; nf++)
                ss += S[nf][2 * rr] * S[nf][2 * rr] + S[nf][2 * rr + 1] * S[nf][2 * rr + 1];
            ss += __shfl_xor_sync(0xffffffffu, ss, 1);
            ss += __shfl_xor_sync(0xffffffffu, ss, 2);
            float inv = 1.0f / fmaxf(sqrtf(ss), 1e-12f);
            int row = r0 + mw * 16 + gid + rr * 8;
            int bb = row >> 11, t = row & 2047;
            size_t base = (((size_t)bb * HEADS + bx * 2 + nh) * NSEQ + t) * DH;
            #pragma unroll
            for (int nf = 0; nf < 8; nf++) {
                float2 v = make_float2(S[nf][2 * rr] * inv, S[nf][2 * rr + 1] * inv);
                *(float2*)&g_q[base + nf * 8 + 2 * tig] = v;
            }
        }
        return;
    }

    const bool is_k = (bx == 4);
    gemm_core_t<8, 1>(g_xf, g_wkvf, r0 >> 4, is_k ? 0 : 8, DIM >> 4, AF, BF, S);
    const int colw = nh * 32;
    const int bbr = r0 >> 11, ktr = (r0 & 2047) >> 6;
    const size_t obase = ((size_t)bbr * NT + ktr) * 1024;

    if (is_k) {
        __syncthreads();
        #pragma unroll
        for (int rr = 0; rr < 2; rr++) {
            float ss = 0.f;
            #pragma unroll
            for (int nf = 0; nf < 4; nf++)
                ss += S[nf][2 * rr] * S[nf][2 * rr] + S[nf][2 * rr + 1] * S[nf][2 * rr + 1];
            ss += __shfl_xor_sync(0xffffffffu, ss, 1);
            ss += __shfl_xor_sync(0xffffffffu, ss, 2);
            if (tig == 0) ssbuf[nh * 64 + mw * 16 + gid + rr * 8] = ss;
        }
        __syncthreads();
        #pragma unroll
        for (int rr = 0; rr < 2; rr++) {
            int rloc = mw * 16 + gid + rr * 8;
            float ss = ssbuf[rloc] + ssbuf[64 + rloc];
            float inv = 1.0f / fmaxf(sqrtf(ss), 1e-12f);
            int nfp = mw * 2 + rr;
            #pragma unroll
            for (int p = 0; p < 2; p++) {
                float a0 = S[2 * p][2 * rr] * inv,     a1 = S[2 * p][2 * rr + 1] * inv;
                float c0 = S[2 * p + 1][2 * rr] * inv, c1 = S[2 * p + 1][2 * rr + 1] * inv;
                uint32_t bh0 = h2bits(__floats2half2_rn(a0, a1));
                uint32_t bh1 = h2bits(__floats2half2_rn(c0, c1));
                int kfp = nh * 2 + p;
                g_kf[obase + (nfp * 4 + kfp) * 32 + lane] = make_uint2(bh0, bh1);
            }
        }
    } else {
        __syncthreads();
        #pragma unroll
        for (int rr = 0; rr < 2; rr++) {
            int rloc = mw * 16 + gid + rr * 8;
            #pragma unroll
            for (int nf = 0; nf < 4; nf++) {
                vsm[rloc * 68 + colw + nf * 8 + 2 * tig]     = S[nf][2 * rr];
                vsm[rloc * 68 + colw + nf * 8 + 2 * tig + 1] = S[nf][2 * rr + 1];
            }
        }
        __syncthreads();
        #pragma unroll
        for (int it = 0; it < 4; it++) {
            int s = tid + it * 256;
            int kg = s >> 8, nfd = (s >> 5) & 7, ln = s & 31;
            int gd = ln >> 2, tg = ln & 3;
            int key0 = kg * 16 + 2 * tg, d = nfd * 8 + gd;
            uint32_t b0 = h2bits(__floats2half2_rn(vsm[key0 * 68 + d], vsm[(key0 + 1) * 68 + d]));
            uint32_t b1 = h2bits(__floats2half2_rn(vsm[(key0 + 8) * 68 + d], vsm[(key0 + 9) * 68 + d]));
            g_vf[obase + s] = make_uint2(b0, b1);
        }
    }
}

// ---------------------------------------------------------------------------
__global__ __launch_bounds__(256) void gemm_out(float* __restrict__ C)
{
    __shared__ uint32_t AF[2 * 2048];
    __shared__ uint32_t BF[2 * 2048];

    const int tid = threadIdx.x, lane = tid & 31, w = tid >> 5;
    const int mw = w & 3, nh = w >> 2;
    const int gid = lane >> 2, tig = lane & 3;
    const int r0 = blockIdx.y * 64, c0 = blockIdx.x * 128;

    float S[8][4];
    gemm_core_t<16, 0>(g_af, g_woutf, r0 >> 4, c0 >> 3, DIM >> 4, AF, BF, S);
    const int row0 = r0 + mw * 16 + gid;
    const int colw = nh * 64;

    #pragma unroll
    for (int rr = 0; rr < 2; rr++)
        #pragma unroll
        for (int nf = 0; nf < 8; nf++) {
            float2 v = make_float2(S[nf][2 * rr], S[nf][2 * rr + 1]);
            *(float2*)&C[(size_t)(row0 + rr * 8) * DIM + c0 + colw + nf * 8 + 2 * tig] = v;
        }
}

// ---------------------------------------------------------------------------
// Flash attention: mem-attention interleaved into the causal loop as a third
// online-softmax accumulator (merged in epilogue). smem (u32):
// QF 0..4096 | stage0 4096..12800 | stage1 12800..21504 | QS 21504..25856 |
// RM 25856..26048 | RL 26048..26240.  OMG aliases stage0; MEMO aliases stage1.
// ---------------------------------------------------------------------------
#define STB 8704
__global__ __launch_bounds__(256, 2) void attn_mma(const float* __restrict__ memkv,
                                                   const float* __restrict__ rel,
                                                   const float* __restrict__ scale_param)
{
    extern __shared__ uint32_t smu[];
    uint32_t* QF  = smu;
    float* QS   = (float*)(smu + 4096 + 2 * STB);       // 64 x 68
    float* RM   = (float*)(smu + 4096 + 2 * STB + 4352);// 192
    float* RL   = RM + 192;                             // 192
    float* OMG  = (float*)(smu + 4096);                 // epilogue alias (stage0)
    float* MEMO = (float*)(smu + 4096 + STB);           // epilogue alias (stage1)

    const int bb = blockIdx.x, hh = blockIdx.y;
    const int qt = NT - 1 - (int)blockIdx.z;
    const int tid = threadIdx.x, lane = tid & 31, w = tid >> 5;
    const int mw = w & 3, ng = w >> 2;
    const int g = ng, gtid = tid & 127;
    const int gid = lane >> 2, tig = lane & 3;
    const int il0 = 16 * mw + gid;
    const float scaleL2 = expf(scale_param[hh]) * L2E;

    const uint32_t ks_su[2] = {s2u(smu + 4096 + g * 1024),
                               s2u(smu + 4096 + g * 1024 + STB)};
    const uint32_t vs_su[2] = {s2u(smu + 6144 + g * 1024),
                               s2u(smu + 6144 + g * 1024 + STB)};
    const uint32_t bs_su[2] = {s2u(smu + 8192 + g * 2304),
                               s2u(smu + 8192 + g * 2304 + STB)};
    const float* relrow = rel + ((size_t)hh * NSEQ + (size_t)qt * 64) * NSEQ;
    const uint4* ktileb = (const uint4*)(g_kf + (size_t)bb * NT * 1024 + g * 512);
    const uint4* vtileb = (const uint4*)(g_vf + (size_t)bb * NT * 1024 + g * 512);

    // ---- prefetch tile 0 into stage 0 ----
    {
        #pragma unroll
        for (int it = 0; it < 2; it++)
            cpa16(ks_su[0] + (gtid + it * 128) * 16, ktileb + gtid + it * 128);
        #pragma unroll
        for (int it = 0; it < 2; it++)
            cpa16(vs_su[0] + (gtid + it * 128) * 16, vtileb + gtid + it * 128);
        const float* bsrc = relrow + g * 32;
        #pragma unroll
        for (int it = 0; it < 4; it++) {
            int c = gtid + it * 128;
            int r = c >> 3, c4 = c & 7;
            cpa16(bs_su[0] + (r * 36 + c4 * 4) * 4, bsrc + (size_t)r * NSEQ + c4 * 4);
        }
        asm volatile("cp.async.commit_group;" ::: "memory");
    }

    // ---- stage Q rows into QS; build QF frags (ng==0) ----
    const float* qbase = g_q + (((size_t)bb * HEADS + hh) * NSEQ + (size_t)qt * 64) * DH;
    #pragma unroll
    for (int it = 0; it < 4; it++) {
        int s4 = tid + it * 256;                // 1024 float4
        int row = s4 >> 4, c4 = (s4 & 15) * 4;
        float4 v = *(const float4*)&qbase[row * DH + c4];
        *(float4*)&QS[row * 68 + c4] = v;
    }
    if (ng == 0) {
        #pragma unroll
        for (int kf = 0; kf < 4; kf++) {
            int d0 = kf * 16 + 2 * tig;
            float2 q00 = *(const float2*)&qbase[il0 * DH + d0];
            float2 q10 = *(const float2*)&qbase[(il0 + 8) * DH + d0];
            float2 q01 = *(const float2*)&qbase[il0 * DH + d0 + 8];
            float2 q11 = *(const float2*)&qbase[(il0 + 8) * DH + d0 + 8];
            uint32_t al0, al1, al2, al3;
            uint32_t ah0 = split_pair_h(q00.x, q00.y, al0);
            uint32_t ah1 = split_pair_h(q10.x, q10.y, al1);
            uint32_t ah2 = split_pair_h(q01.x, q01.y, al2);
            uint32_t ah3 = split_pair_h(q11.x, q11.y, al3);
            uint32_t* qp = &QF[((mw * 4 + kf) * 32 + lane) * 8];
            *(uint4*)qp       = make_uint4(ah0, ah1, ah2, ah3);
            *(uint4*)(qp + 4) = make_uint4(al0, al1, al2, al3);
        }
    }
    __syncthreads();

    // ---- accumulators: causal (frag) + mem (SIMT quad) ----
    float O[8][4] = {}, m_r[2], l_r[2];
    m_r[0] = m_r[1] = -3.0e38f;
    l_r[0] = l_r[1] = 0.f;

    const int qi = tid >> 2, qtr = tid & 3;
    float mT = -3.0e38f, lT = 0.f, accT[16];
    #pragma unroll
    for (int u = 0; u < 16; u++) accT[u] = 0.f;
    int cdone = 0;
    const float* mkq = memkv + ((((size_t)bb * HEADS + hh) * NSEQ
                               + (size_t)qt * 64 + qi) * KRET) * 128 + qtr * 16;

    // ---- causal tiles with interleaved mem-key chunks ----
    for (int kt = 0; kt <= qt; kt++) {
        const int cur = kt & 1;
        asm volatile("bar.sync %0, 128;" :: "r"(1 + g) : "memory");
        if (kt + 1 <= qt) {
            const int st = cur ^ 1;
            const uint4* ks = ktileb + (size_t)(kt + 1) * 256;
            #pragma unroll
            for (int it = 0; it < 2; it++)
                cpa16(ks_su[st] + (gtid + it * 128) * 16, ks + gtid + it * 128);
            const uint4* vs = vtileb + (size_t)(kt + 1) * 256;
            #pragma unroll
            for (int it = 0; it < 2; it++)
                cpa16(vs_su[st] + (gtid + it * 128) * 16, vs + gtid + it * 128);
            const float* bsrc = relrow + (size_t)(kt + 1) * 64 + g * 32;
            #pragma unroll
            for (int it = 0; it < 4; it++) {
                int c = gtid + it * 128;
                int r = c >> 3, c4 = c & 7;
                cpa16(bs_su[st] + (r * 36 + c4 * 4) * 4, bsrc + (size_t)r * NSEQ + c4 * 4);
            }
        }
        asm volatile("cp.async.commit_group;" ::: "memory");
        asm volatile("cp.async.wait_group 1;" ::: "memory");
        asm volatile("bar.sync %0, 128;" :: "r"(1 + g) : "memory");

        const uint32_t* KSc = smu + 4096 + g * 1024 + cur * STB;
        const uint32_t* VSc = smu + 6144 + g * 1024 + cur * STB;
        const float*    BSc = (const float*)(smu + 8192 + g * 2304 + cur * STB);

        float S[4][4] = {};
        #pragma unroll
        for (int kf = 0; kf < 4; kf++) {
            const uint32_t* qp = &QF[((mw * 4 + kf) * 32 + lane) * 8];
            uint4 ah = *(const uint4*)qp;
            uint4 al = *(const uint4*)(qp + 4);
            #pragma unroll
            for (int nf = 0; nf < 4; nf++) {
                uint2 kb = *(const uint2*)&KSc[((nf * 4 + kf) * 32 + lane) * 2];
                mma16(S[nf], ah.x, ah.y, ah.z, ah.w, kb.x, kb.y);
                mma16(S[nf], al.x, al.y, al.z, al.w, kb.x, kb.y);
            }
        }

        uint32_t ph[4][2];
        #pragma unroll
        for (int rr = 0; rr < 2; rr++) {
            int il = il0 + rr * 8;
            float mx = -3.0e38f;
            #pragma unroll
            for (int nf = 0; nf < 4; nf++) {
                int colb = g * 32 + nf * 8 + 2 * tig;
                float2 b2 = *(const float2*)&BSc[il * 36 + nf * 8 + 2 * tig];
                float s0 = fmaf(S[nf][2 * rr], scaleL2, b2.x * L2E);
                float s1 = fmaf(S[nf][2 * rr + 1], scaleL2, b2.y * L2E);
                if (kt == qt) {
                    if (colb     > il) s0 = -3.0e38f;
                    if (colb + 1 > il) s1 = -3.0e38f;
                }
                S[nf][2 * rr] = s0; S[nf][2 * rr + 1] = s1;
                mx = fmaxf(mx, fmaxf(s0, s1));
            }
            mx = fmaxf(mx, __shfl_xor_sync(0xffffffffu, mx, 1));
            mx = fmaxf(mx, __shfl_xor_sync(0xffffffffu, mx, 2));
            float mnew = fmaxf(m_r[rr], mx);
            float f = ex2(m_r[rr] - mnew);
            m_r[rr] = mnew;
            float ls = 0.f;
            #pragma unroll
            for (int nf = 0; nf < 4; nf++) {
                float p0 = ex2(S[nf][2 * rr] - mnew);
                float p1 = ex2(S[nf][2 * rr + 1] - mnew);
                ls += p0 + p1;
                ph[nf][rr] = h2bits(__floats2half2_rn(p0, p1));
            }
            #pragma unroll
            for (int nf = 0; nf < 8; nf++) {
                O[nf][2 * rr]     *= f;
                O[nf][2 * rr + 1] *= f;
            }
            ls += __shfl_xor_sync(0xffffffffu, ls, 1);
            ls += __shfl_xor_sync(0xffffffffu, ls, 2);
            l_r[rr] = l_r[rr] * f + ls;
        }

        #pragma unroll
        for (int kfl = 0; kfl < 2; kfl++) {
            uint32_t a0 = ph[2 * kfl][0], a1 = ph[2 * kfl][1];
            uint32_t a2 = ph[2 * kfl + 1][0], a3 = ph[2 * kfl + 1][1];
            #pragma unroll
            for (int nfd = 0; nfd < 8; nfd++) {
                uint2 vb = *(const uint2*)&VSc[((kfl * 8 + nfd) * 32 + lane) * 2];
                mma16(O[nfd], a0, a1, a2, a3, vb.x, vb.y);
            }
        }

        // ---- interleaved mem-key chunks (SIMT fp32, online softmax) ----
        int cend = ((kt + 1) * 8 + qt) / (qt + 1);
        if (cend > 8) cend = 8;
        for (; cdone < cend; cdone++) {
            float qv[16];
            *(float4*)&qv[0]  = *(const float4*)&QS[qi * 68 + qtr * 16];
            *(float4*)&qv[4]  = *(const float4*)&QS[qi * 68 + qtr * 16 + 4];
            *(float4*)&qv[8]  = *(const float4*)&QS[qi * 68 + qtr * 16 + 8];
            *(float4*)&qv[12] = *(const float4*)&QS[qi * 68 + qtr * 16 + 12];
            const float* kp = mkq + (size_t)cdone * 512;
            #pragma unroll
            for (int j = 0; j < 4; j++) {
                const float* kj = kp + j * 128;
                float4 k0 = *(const float4*)kj;
                float4 k1 = *(const float4*)(kj + 4);
                float4 k2 = *(const float4*)(kj + 8);
                float4 k3 = *(const float4*)(kj + 12);
                float s = qv[0]*k0.x + qv[1]*k0.y + qv[2]*k0.z + qv[3]*k0.w
                        + qv[4]*k1.x + qv[5]*k1.y + qv[6]*k1.z + qv[7]*k1.w
                        + qv[8]*k2.x + qv[9]*k2.y + qv[10]*k2.z + qv[11]*k2.w
                        + qv[12]*k3.x + qv[13]*k3.y + qv[14]*k3.z + qv[15]*k3.w;
                s += __shfl_xor_sync(0xffffffffu, s, 1);
                s += __shfl_xor_sync(0xffffffffu, s, 2);
                s *= scaleL2;
                float mnew = fmaxf(mT, s);
                float f = ex2(mT - mnew);
                float p = ex2(s - mnew);
                lT = lT * f + p;
                mT = mnew;
                float4 v0 = *(const float4*)(kj + 64);
                float4 v1 = *(const float4*)(kj + 68);
                float4 v2 = *(const float4*)(kj + 72);
                float4 v3 = *(const float4*)(kj + 76);
                accT[0]  = accT[0]*f  + p*v0.x; accT[1]  = accT[1]*f  + p*v0.y;
                accT[2]  = accT[2]*f  + p*v0.z; accT[3]  = accT[3]*f  + p*v0.w;
                accT[4]  = accT[4]*f  + p*v1.x; accT[5]  = accT[5]*f  + p*v1.y;
                accT[6]  = accT[6]*f  + p*v1.z; accT[7]  = accT[7]*f  + p*v1.w;
                accT[8]  = accT[8]*f  + p*v2.x; accT[9]  = accT[9]*f  + p*v2.y;
                accT[10] = accT[10]*f + p*v2.z; accT[11] = accT[11]*f + p*v2.w;
                accT[12] = accT[12]*f + p*v3.x; accT[13] = accT[13]*f + p*v3.y;
                accT[14] = accT[14]*f + p*v3.z; accT[15] = accT[15]*f + p*v3.w;
            }
        }
    }

    // ---- 3-way merge (ng0, ng1, mem) and emit gemm3 A-fragments ----
    asm volatile("cp.async.wait_group 0;" ::: "memory");
    __syncthreads();
    // mem contribution -> MEMO (stage1 alias, now dead)
    #pragma unroll
    for (int u = 0; u < 4; u++)
        *(float4*)&MEMO[qi * 68 + qtr * 16 + u * 4] = *(float4*)&accT[u * 4];
    if (!qtr) { RM[128 + qi] = mT; RL[128 + qi] = lT; }
    if (ng == 1) {
        #pragma unroll
        for (int rr = 0; rr < 2; rr++) {
            int il = il0 + rr * 8;
            RM[64 + il] = m_r[rr];
            RL[64 + il] = l_r[rr];
            #pragma unroll
            for (int nf = 0; nf < 8; nf++) {
                float2 v = make_float2(O[nf][2 * rr], O[nf][2 * rr + 1]);
                *(float2*)&OMG[il * 72 + nf * 8 + 2 * tig] = v;
            }
        }
    }
    __syncthreads();
    if (ng == 0) {
        #pragma unroll
        for (int rr = 0; rr < 2; rr++) {
            int il = il0 + rr * 8;
            float m1 = RM[64 + il], l1 = RL[64 + il];
            float mm = RM[128 + il], lm = RL[128 + il];
            float m = fmaxf(fmaxf(m_r[rr], m1), mm);
            float f0 = ex2(m_r[rr] - m), f1 = ex2(m1 - m), fm = ex2(mm - m);
            float inv = 1.0f / (l_r[rr] * f0 + l1 * f1 + lm * fm);
            #pragma unroll
            for (int nf = 0; nf < 8; nf++) {
                float2 o1 = *(const float2*)&OMG[il * 72 + nf * 8 + 2 * tig];
                float2 om = *(const float2*)&MEMO[il * 68 + nf * 8 + 2 * tig];
                O[nf][2 * rr]     = (O[nf][2 * rr]     * f0 + o1.x * f1 + om.x * fm) * inv;
                O[nf][2 * rr + 1] = (O[nf][2 * rr + 1] * f0 + o1.y * f1 + om.y * fm) * inv;
            }
        }
        int band = bb * 128 + qt * 4 + mw;
        #pragma unroll
        for (int kf = 0; kf < 4; kf++) {
            uint32_t l0, l1, l2, l3;
            uint32_t h0 = split_pair_h(O[2 * kf][0],     O[2 * kf][1],     l0);
            uint32_t h1 = split_pair_h(O[2 * kf][2],     O[2 * kf][3],     l1);
            uint32_t h2 = split_pair_h(O[2 * kf + 1][0], O[2 * kf + 1][1], l2);
            uint32_t h3 = split_pair_h(O[2 * kf + 1][2], O[2 * kf + 1][3], l3);
            size_t slot = ((size_t)band * 32 + (hh * 4 + kf)) * 32 + lane;
            *(uint4*)&g_af[slot * 8]     = make_uint4(h0, h1, h2, h3);
            *(uint4*)&g_af[slot * 8 + 4] = make_uint4(l0, l1, l2, l3);
        }
    }
}

// ---------------------------------------------------------------------------
extern "C" void kernel_launch(void* const* d_in, const int* in_sizes, int n_in,
                              void* d_out, int out_size)
{
    const float* x      = (const float*)d_in[0];
    const float* memkv  = (const float*)d_in[1];
    const float* rel    = (const float*)d_in[3];
    const float* Wq     = (const float*)d_in[4];
    const float* Wkv    = (const float*)d_in[5];
    const float* Wout   = (const float*)d_in[6];
    const float* scalep = (const float*)d_in[7];
    float* out = (float*)d_out;

    const int SMEM = (4096 + 2 * STB + 4352 + 384) * (int)sizeof(uint32_t);  // 104960 B
    cudaFuncSetAttribute(attn_mma, cudaFuncAttributeMaxDynamicSharedMemorySize, SMEM);

    const int M = BATCH * NSEQ;
    pack_in<<<1792, 256>>>(x, Wq, Wkv, Wout);
    gemm_qkv<<<dim3(6, M / 64), 256>>>();
    attn_mma<<<dim3(BATCH, HEADS, NT), 256, SMEM>>>(memkv, rel, scalep);
    gemm_out<<<dim3(4, M / 64), 256>>>(out);
}

// round 16
// speedup vs baseline: 1.2721x; 1.2721x over previous
#include <cuda_runtime.h>
#include <cuda_fp16.h>
#include <math.h>
#include <stdint.h>

#define NSEQ 2048
#define BATCH 2
#define HEADS 8
#define DH 64
#define KRET 32
#define DIM 512
#define NT 32
#define L2E 1.4426950408889634f

__device__ float g_q[(size_t)BATCH * HEADS * NSEQ * DH];
__device__ uint2 g_kf[(size_t)BATCH * NT * 1024];          // K frags: hi only
__device__ uint2 g_vf[(size_t)BATCH * NT * 1024];
__device__ uint32_t g_xf[(size_t)256 * 32 * 32 * 8];
__device__ uint32_t g_af[(size_t)256 * 32 * 32 * 8];
__device__ uint32_t g_wqf[(size_t)64 * 32 * 32 * 4];
__device__ uint32_t g_wkvf[(size_t)16 * 32 * 32 * 4];
__device__ uint32_t g_woutf[(size_t)64 * 32 * 32 * 2];     // Wout frags: hi only

__device__ __forceinline__ void mma16(float* d, uint32_t a0, uint32_t a1, uint32_t a2,
                                      uint32_t a3, uint32_t b0, uint32_t b1) {
    asm volatile("mma.sync.aligned.m16n8k16.row.col.f32.f16.f16.f32 "
        "{%0,%1,%2,%3}, {%4,%5,%6,%7}, {%8,%9}, {%0,%1,%2,%3};"
        : "+f"(d[0]), "+f"(d[1]), "+f"(d[2]), "+f"(d[3])
        : "r"(a0), "r"(a1), "r"(a2), "r"(a3), "r"(b0), "r"(b1));
}
__device__ __forceinline__ float ex2(float x) {
    float r; asm("ex2.approx.f32 %0, %1;" : "=f"(r) : "f"(x)); return r;
}
__device__ __forceinline__ uint32_t h2bits(__half2 h) {
    uint32_t u; *(__half2*)&u = h; return u;
}
__device__ __forceinline__ uint32_t split_pair_h(float a, float b, uint32_t& lo) {
    __half ha = __float2half_rn(a), hb = __float2half_rn(b);
    float ra = a - __half2float(ha), rb = b - __half2float(hb);
    lo = h2bits(__floats2half2_rn(ra, rb));
    return h2bits(__halves2half2(ha, hb));
}
__device__ __forceinline__ uint32_t s2u(const void* p) {
    return (uint32_t)__cvta_generic_to_shared(p);
}
__device__ __forceinline__ void cpa16(uint32_t s, const void* g) {
    asm volatile("cp.async.cg.shared.global [%0], [%1], 16;" :: "r"(s), "l"(g) : "memory");
}

// ---------------------------------------------------------------------------
// Merged input pack. Wout packed hi-only (uint2 per slot).
// ---------------------------------------------------------------------------
__global__ __launch_bounds__(256) void pack_in(const float* __restrict__ x,
                                               const float* __restrict__ Wq,
                                               const float* __restrict__ Wkv,
                                               const float* __restrict__ Wout)
{
    int bx = blockIdx.x;
    if (bx < 1024) {
        int s = bx * 256 + threadIdx.x;
        int band = s >> 10, rem = s & 1023;
        int kfg = rem >> 5, ln = rem & 31;
        int gid = ln >> 2, tig = ln & 3;
        const float* base = x + (size_t)(band * 16 + gid) * DIM + kfg * 16 + 2 * tig;
        float2 x00 = *(const float2*)base;
        float2 x10 = *(const float2*)(base + 8 * DIM);
        float2 x01 = *(const float2*)(base + 8);
        float2 x11 = *(const float2*)(base + 8 * DIM + 8);
        uint32_t l0, l1, l2, l3;
        uint32_t h0 = split_pair_h(x00.x, x00.y, l0);
        uint32_t h1 = split_pair_h(x10.x, x10.y, l1);
        uint32_t h2 = split_pair_h(x01.x, x01.y, l2);
        uint32_t h3 = split_pair_h(x11.x, x11.y, l3);
        *(uint4*)&g_xf[(size_t)s * 8]     = make_uint4(h0, h1, h2, h3);
        *(uint4*)&g_xf[(size_t)s * 8 + 4] = make_uint4(l0, l1, l2, l3);
    } else {
        int sel = (bx - 1024) >> 8;
        const float* W = sel == 0 ? Wq : (sel == 1 ? Wkv : Wout);
        int N = (sel == 1) ? 128 : 512;
        int s = ((bx - 1024) & 255) * 256 + threadIdx.x;
        if (s >= (N / 8) * 1024) return;
        int nfg = s >> 10, rem = s & 1023;
        int kfg = rem >> 5, ln = rem & 31;
        int gid = ln >> 2, tig = ln & 3;
        int n = nfg * 8 + gid, k0 = kfg * 16 + 2 * tig;
        uint32_t bl0, bl1;
        uint32_t bh0 = split_pair_h(W[(size_t)k0 * N + n], W[(size_t)(k0 + 1) * N + n], bl0);
        uint32_t bh1 = split_pair_h(W[(size_t)(k0 + 8) * N + n], W[(size_t)(k0 + 9) * N + n], bl1);
        if (sel == 2) {
            *(uint2*)&g_woutf[(size_t)s * 2] = make_uint2(bh0, bh1);
        } else {
            uint32_t* out = sel == 0 ? g_wqf : g_wkvf;
            *(uint4*)&out[(size_t)s * 4] = make_uint4(bh0, bh1, bl0, bl1);
        }
    }
}

// ---------------------------------------------------------------------------
// Templated GEMM mainloop: 64 x (NF*8) tile, 256 threads.
// SPLITB=1: B frags uint4 (hi+lo), 3-mma. SPLITB=0: B frags uint2 (hi), 2-mma.
// ---------------------------------------------------------------------------
template <int NF, int SPLITB>
__device__ __forceinline__ void gemm_core_t(const uint32_t* __restrict__ APK,
                                            const uint32_t* __restrict__ BPK,
                                            int band0, int nf0, int KFG,
                                            uint32_t* AF, uint32_t* BF,
                                            float S[][4])
{
    const int tid = threadIdx.x, lane = tid & 31, w = tid >> 5;
    const int mw = w & 3, nh = w >> 2;
    const int nslab = KFG >> 1;
    const int BSTG = NF * (SPLITB ? 256 : 128);
    const int BITER = SPLITB ? NF / 4 : NF / 8;
    const uint32_t a_su[2] = {s2u(AF), s2u(AF + 2048)};
    const uint32_t b_su[2] = {s2u(BF), s2u(BF + BSTG)};

    #pragma unroll
    for (int r = 0; r < NF / 2; r++)
        #pragma unroll
        for (int c = 0; c < 4; c++) S[r][c] = 0.f;

    #pragma unroll
    for (int it = 0; it < 2; it++) {
        int idx = tid + it * 256;
        int kf2 = idx >> 8, mb = (idx >> 6) & 3, ln = (idx >> 1) & 31, hf = idx & 1;
        cpa16(a_su[0] + (((kf2 * 4 + mb) * 32 + ln) * 8 + hf * 4) * 4,
              APK + ((size_t)((band0 + mb) * KFG + kf2) * 32 + ln) * 8 + hf * 4);
    }
    #pragma unroll
    for (int it = 0; it < BITER; it++) {
        int idx = tid + it * 256;
        if (SPLITB) {
            int kf2 = idx / (32 * NF), nf = (idx >> 5) % NF, lnb = idx & 31;
            cpa16(b_su[0] + ((kf2 * NF + nf) * 32 + lnb) * 16,
                  BPK + ((size_t)((nf0 + nf) * KFG + kf2) * 32 + lnb) * 4);
        } else {
            int kf2 = idx / (NF * 16), rem = idx % (NF * 16);
            int nf = rem >> 4, cq = rem & 15;
            cpa16(b_su[0] + ((kf2 * NF + nf) * 64 + cq * 4) * 4,
                  BPK + ((size_t)(nf0 + nf) * KFG + kf2) * 64 + cq * 4);
        }
    }
    asm volatile("cp.async.commit_group;" ::: "memory");

    for (int ks = 0; ks < nslab; ks++) {
        const int cur = ks & 1;
        __syncthreads();
        if (ks + 1 < nslab) {
            const int st = cur ^ 1;
            #pragma unroll
            for (int it = 0; it < 2; it++) {
                int idx = tid + it * 256;
                int kf2 = idx >> 8, mb = (idx >> 6) & 3, ln = (idx >> 1) & 31, hf = idx & 1;
                int kfg = (ks + 1) * 2 + kf2;
                cpa16(a_su[st] + (((kf2 * 4 + mb) * 32 + ln) * 8 + hf * 4) * 4,
                      APK + ((size_t)((band0 + mb) * KFG + kfg) * 32 + ln) * 8 + hf * 4);
            }
            #pragma unroll
            for (int it = 0; it < BITER; it++) {
                int idx = tid + it * 256;
                if (SPLITB) {
                    int kf2 = idx / (32 * NF), nf = (idx >> 5) % NF, lnb = idx & 31;
                    int kfg = (ks + 1) * 2 + kf2;
                    cpa16(b_su[st] + ((kf2 * NF + nf) * 32 + lnb) * 16,
                          BPK + ((size_t)((nf0 + nf) * KFG + kfg) * 32 + lnb) * 4);
                } else {
                    int kf2 = idx / (NF * 16), rem = idx % (NF * 16);
                    int nf = rem >> 4, cq = rem & 15;
                    int kfg = (ks + 1) * 2 + kf2;
                    cpa16(b_su[st] + ((kf2 * NF + nf) * 64 + cq * 4) * 4,
                          BPK + ((size_t)(nf0 + nf) * KFG + kfg) * 64 + cq * 4);
                }
            }
        }
        asm volatile("cp.async.commit_group;" ::: "memory");
        asm volatile("cp.async.wait_group 1;" ::: "memory");
        __syncthreads();

        uint32_t* AFc = AF + cur * 2048;
        uint32_t* BFc = BF + cur * BSTG;
        #pragma unroll
        for (int kf2 = 0; kf2 < 2; kf2++) {
            const uint32_t* ap = &AFc[((kf2 * 4 + mw) * 32 + lane) * 8];
            uint4 ah = *(const uint4*)ap;
            uint4 al = *(const uint4*)(ap + 4);
            #pragma unroll
            for (int nf = 0; nf < NF / 2; nf++) {
                if (SPLITB) {
                    uint4 kb = *(const uint4*)&BFc[((kf2 * NF + nh * (NF / 2) + nf) * 32 + lane) * 4];
                    mma16(S[nf], ah.x, ah.y, ah.z, ah.w, kb.x, kb.y);
                    mma16(S[nf], al.x, al.y, al.z, al.w, kb.x, kb.y);
                    mma16(S[nf], ah.x, ah.y, ah.z, ah.w, kb.z, kb.w);
                } else {
                    uint2 kb = *(const uint2*)&BFc[((kf2 * NF + nh * (NF / 2) + nf) * 32 + lane) * 2];
                    mma16(S[nf], ah.x, ah.y, ah.z, ah.w, kb.x, kb.y);
                    mma16(S[nf], al.x, al.y, al.z, al.w, kb.x, kb.y);
                }
            }
        }
    }
}

// ---------------------------------------------------------------------------
// Fused QKV GEMM: grid (6, 64). bx<4 -> Wq 128-wide; bx==4 -> K; bx==5 -> V.
// ---------------------------------------------------------------------------
__global__ __launch_bounds__(256) void gemm_qkv()
{
    __shared__ uint32_t AF[2 * 2048];
    __shared__ uint32_t BF[2 * 4096];
    float* vsm   = (float*)BF;
    float* ssbuf = (float*)AF;

    const int tid = threadIdx.x, lane = tid & 31, w = tid >> 5;
    const int mw = w & 3, nh = w >> 2;
    const int gid = lane >> 2, tig = lane & 3;
    const int r0 = blockIdx.y * 64;
    const int bx = blockIdx.x;

    float S[8][4];

    if (bx < 4) {
        gemm_core_t<16, 1>(g_xf, g_wqf, r0 >> 4, bx * 16, DIM >> 4, AF, BF, S);
        #pragma unroll
        for (int rr = 0; rr < 2; rr++) {
            float ss = 0.f;
            #pragma unroll
            for (int nf = 0; nf < 8; nf++)
                ss += S[nf][2 * rr] * S[nf][2 * rr] + S[nf][2 * rr + 1] * S[nf][2 * rr + 1];
            ss += __shfl_xor_sync(0xffffffffu, ss, 1);
            ss += __shfl_xor_sync(0xffffffffu, ss, 2);
            float inv = 1.0f / fmaxf(sqrtf(ss), 1e-12f);
            int row = r0 + mw * 16 + gid + rr * 8;
            int bb = row >> 11, t = row & 2047;
            size_t base = (((size_t)bb * HEADS + bx * 2 + nh) * NSEQ + t) * DH;
            #pragma unroll
            for (int nf = 0; nf < 8; nf++) {
                float2 v = make_float2(S[nf][2 * rr] * inv, S[nf][2 * rr + 1] * inv);
                *(float2*)&g_q[base + nf * 8 + 2 * tig] = v;
            }
        }
        return;
    }

    const bool is_k = (bx == 4);
    gemm_core_t<8, 1>(g_xf, g_wkvf, r0 >> 4, is_k ? 0 : 8, DIM >> 4, AF, BF, S);
    const int colw = nh * 32;
    const int bbr = r0 >> 11, ktr = (r0 & 2047) >> 6;
    const size_t obase = ((size_t)bbr * NT + ktr) * 1024;

    if (is_k) {
        __syncthreads();
        #pragma unroll
        for (int rr = 0; rr < 2; rr++) {
            float ss = 0.f;
            #pragma unroll
            for (int nf = 0; nf < 4; nf++)
                ss += S[nf][2 * rr] * S[nf][2 * rr] + S[nf][2 * rr + 1] * S[nf][2 * rr + 1];
            ss += __shfl_xor_sync(0xffffffffu, ss, 1);
            ss += __shfl_xor_sync(0xffffffffu, ss, 2);
            if (tig == 0) ssbuf[nh * 64 + mw * 16 + gid + rr * 8] = ss;
        }
        __syncthreads();
        #pragma unroll
        for (int rr = 0; rr < 2; rr++) {
            int rloc = mw * 16 + gid + rr * 8;
            float ss = ssbuf[rloc] + ssbuf[64 + rloc];
            float inv = 1.0f / fmaxf(sqrtf(ss), 1e-12f);
            int nfp = mw * 2 + rr;
            #pragma unroll
            for (int p = 0; p < 2; p++) {
                float a0 = S[2 * p][2 * rr] * inv,     a1 = S[2 * p][2 * rr + 1] * inv;
                float c0 = S[2 * p + 1][2 * rr] * inv, c1 = S[2 * p + 1][2 * rr + 1] * inv;
                uint32_t bh0 = h2bits(__floats2half2_rn(a0, a1));
                uint32_t bh1 = h2bits(__floats2half2_rn(c0, c1));
                int kfp = nh * 2 + p;
                g_kf[obase + (nfp * 4 + kfp) * 32 + lane] = make_uint2(bh0, bh1);
            }
        }
    } else {
        __syncthreads();
        #pragma unroll
        for (int rr = 0; rr < 2; rr++) {
            int rloc = mw * 16 + gid + rr * 8;
            #pragma unroll
            for (int nf = 0; nf < 4; nf++) {
                vsm[rloc * 68 + colw + nf * 8 + 2 * tig]     = S[nf][2 * rr];
                vsm[rloc * 68 + colw + nf * 8 + 2 * tig + 1] = S[nf][2 * rr + 1];
            }
        }
        __syncthreads();
        #pragma unroll
        for (int it = 0; it < 4; it++) {
            int s = tid + it * 256;
            int kg = s >> 8, nfd = (s >> 5) & 7, ln = s & 31;
            int gd = ln >> 2, tg = ln & 3;
            int key0 = kg * 16 + 2 * tg, d = nfd * 8 + gd;
            uint32_t b0 = h2bits(__floats2half2_rn(vsm[key0 * 68 + d], vsm[(key0 + 1) * 68 + d]));
            uint32_t b1 = h2bits(__floats2half2_rn(vsm[(key0 + 8) * 68 + d], vsm[(key0 + 9) * 68 + d]));
            g_vf[obase + s] = make_uint2(b0, b1);
        }
    }
}

// ---------------------------------------------------------------------------
// Output GEMM: 64x128 tiles, hi-only B (2-mma).
// ---------------------------------------------------------------------------
__global__ __launch_bounds__(256) void gemm_out(float* __restrict__ C)
{
    __shared__ uint32_t AF[2 * 2048];
    __shared__ uint32_t BF[2 * 2048];

    const int tid = threadIdx.x, lane = tid & 31, w = tid >> 5;
    const int mw = w & 3, nh = w >> 2;
    const int gid = lane >> 2, tig = lane & 3;
    const int r0 = blockIdx.y * 64, c0 = blockIdx.x * 128;

    float S[8][4];
    gemm_core_t<16, 0>(g_af, g_woutf, r0 >> 4, c0 >> 3, DIM >> 4, AF, BF, S);
    const int row0 = r0 + mw * 16 + gid;
    const int colw = nh * 64;

    #pragma unroll
    for (int rr = 0; rr < 2; rr++)
        #pragma unroll
        for (int nf = 0; nf < 8; nf++) {
            float2 v = make_float2(S[nf][2 * rr], S[nf][2 * rr + 1]);
            *(float2*)&C[(size_t)(row0 + rr * 8) * DIM + c0 + colw + nf * 8 + 2 * tig] = v;
        }
}

// ---------------------------------------------------------------------------
// Flash attention (R14 structure: serial mem prologue seeds ng0, K hi-only
// 2-mma loop). Prologue loops unrolled for MLP.
// ---------------------------------------------------------------------------
#define STB 8704
__global__ __launch_bounds__(256, 2) void attn_mma(const float* __restrict__ memkv,
                                                   const float* __restrict__ rel,
                                                   const float* __restrict__ scale_param)
{
    extern __shared__ uint32_t smu[];
    uint32_t* QF  = smu;
    float* PMEM = (float*)(smu + 4096 + STB);
    float* OSM  = (float*)(smu + 4096 + STB + 2304);
    float* OMG  = (float*)(smu + 4096);
    float* RM   = (float*)(smu + 4096 + 2 * STB);
    float* RL   = RM + 128;

    const int bb = blockIdx.x, hh = blockIdx.y;
    const int qt = NT - 1 - (int)blockIdx.z;
    const int tid = threadIdx.x, lane = tid & 31, w = tid >> 5;
    const int mw = w & 3, ng = w >> 2;
    const int g = ng, gtid = tid & 127;
    const int gid = lane >> 2, tig = lane & 3;
    const int il0 = 16 * mw + gid;
    const float scaleL2 = expf(scale_param[hh]) * L2E;

    const uint32_t ks_su[2] = {s2u(smu + 4096 + g * 1024),
                               s2u(smu + 4096 + g * 1024 + STB)};
    const uint32_t vs_su[2] = {s2u(smu + 6144 + g * 1024),
                               s2u(smu + 6144 + g * 1024 + STB)};
    const uint32_t bs_su[2] = {s2u(smu + 8192 + g * 2304),
                               s2u(smu + 8192 + g * 2304 + STB)};
    const float* relrow = rel + ((size_t)hh * NSEQ + (size_t)qt * 64) * NSEQ;
    const uint4* ktileb = (const uint4*)(g_kf + (size_t)bb * NT * 1024 + g * 512);
    const uint4* vtileb = (const uint4*)(g_vf + (size_t)bb * NT * 1024 + g * 512);

    {
        #pragma unroll
        for (int it = 0; it < 2; it++)
            cpa16(ks_su[0] + (gtid + it * 128) * 16, ktileb + gtid + it * 128);
        #pragma unroll
        for (int it = 0; it < 2; it++)
            cpa16(vs_su[0] + (gtid + it * 128) * 16, vtileb + gtid + it * 128);
        const float* bsrc = relrow + g * 32;
        #pragma unroll
        for (int it = 0; it < 4; it++) {
            int c = gtid + it * 128;
            int r = c >> 3, c4 = c & 7;
            cpa16(bs_su[0] + (r * 36 + c4 * 4) * 4, bsrc + (size_t)r * NSEQ + c4 * 4);
        }
        asm volatile("cp.async.commit_group;" ::: "memory");
    }

    const float* qbase = g_q + (((size_t)bb * HEADS + hh) * NSEQ + (size_t)qt * 64) * DH;
    if (ng == 0) {
        #pragma unroll
        for (int kf = 0; kf < 4; kf++) {
            int d0 = kf * 16 + 2 * tig;
            float2 q00 = *(const float2*)&qbase[il0 * DH + d0];
            float2 q10 = *(const float2*)&qbase[(il0 + 8) * DH + d0];
            float2 q01 = *(const float2*)&qbase[il0 * DH + d0 + 8];
            float2 q11 = *(const float2*)&qbase[(il0 + 8) * DH + d0 + 8];
            uint32_t al0, al1, al2, al3;
            uint32_t ah0 = split_pair_h(q00.x, q00.y, al0);
            uint32_t ah1 = split_pair_h(q10.x, q10.y, al1);
            uint32_t ah2 = split_pair_h(q01.x, q01.y, al2);
            uint32_t ah3 = split_pair_h(q11.x, q11.y, al3);
            uint32_t* qp = &QF[((mw * 4 + kf) * 32 + lane) * 8];
            *(uint4*)qp       = make_uint4(ah0, ah1, ah2, ah3);
            *(uint4*)(qp + 4) = make_uint4(al0, al1, al2, al3);
        }
    }

    // ---- memory-attention prologue (SIMT fp32), 4 threads per query ----
    {
        int qi = tid >> 2, qtr = tid & 3;
        size_t gi = (size_t)qt * 64 + qi;
        const float* qrow = qbase + qi * DH + qtr * 16;
        float4 q4[4];
        #pragma unroll
        for (int u = 0; u < 4; u++) q4[u] = *(const float4*)&qrow[u * 4];
        const float* mk = memkv + ((((size_t)bb * HEADS + hh) * NSEQ + gi) * KRET) * 128
                        + qtr * 16;
        float sj[8];
        #pragma unroll 4
        for (int j = 0; j < 32; j++) {
            const float* kp = mk + (size_t)j * 128;
            float p = 0.f;
            #pragma unroll
            for (int u = 0; u < 4; u++) {
                float4 k4 = __ldg((const float4*)&kp[u * 4]);
                p += q4[u].x * k4.x + q4[u].y * k4.y + q4[u].z * k4.z + q4[u].w * k4.w;
            }
            p += __shfl_xor_sync(0xffffffffu, p, 1);
            p += __shfl_xor_sync(0xffffffffu, p, 2);
            if ((j & 3) == qtr) sj[j >> 2] = p * scaleL2;
        }
        float mx = -3.0e38f;
        #pragma unroll
        for (int u = 0; u < 8; u++) mx = fmaxf(mx, sj[u]);
        mx = fmaxf(mx, __shfl_xor_sync(0xffffffffu, mx, 1));
        mx = fmaxf(mx, __shfl_xor_sync(0xffffffffu, mx, 2));
        float ls = 0.f;
        #pragma unroll
        for (int u = 0; u < 8; u++) {
            float pe = ex2(sj[u] - mx);
            ls += pe;
            PMEM[qi * 36 + u * 4 + qtr] = pe;
        }
        ls += __shfl_xor_sync(0xffffffffu, ls, 1);
        ls += __shfl_xor_sync(0xffffffffu, ls, 2);
        if (!qtr) { RM[qi] = mx; RL[qi] = ls; }
    }
    __syncthreads();

    {
        int qi = tid >> 2, qtr = tid & 3;
        size_t gi = (size_t)qt * 64 + qi;
        const float* vb = memkv + ((((size_t)bb * HEADS + hh) * NSEQ + gi) * KRET) * 128
                        + 64 + qtr * 16;
        float4 acc[4] = {};
        #pragma unroll 2
        for (int j = 0; j < 32; j++) {
            float p = PMEM[qi * 36 + j];
            #pragma unroll
            for (int u = 0; u < 4; u++) {
                float4 v4 = __ldg((const float4*)&vb[(size_t)j * 128 + u * 4]);
                acc[u].x += p * v4.x; acc[u].y += p * v4.y;
                acc[u].z += p * v4.z; acc[u].w += p * v4.w;
            }
        }
        #pragma unroll
        for (int u = 0; u < 4; u++)
            *(float4*)&OSM[qi * 68 + qtr * 16 + u * 4] = acc[u];
    }
    __syncthreads();

    float O[8][4] = {}, m_r[2], l_r[2];
    if (ng == 0) {
        m_r[0] = RM[il0];     l_r[0] = RL[il0];
        m_r[1] = RM[il0 + 8]; l_r[1] = RL[il0 + 8];
        #pragma unroll
        for (int nf = 0; nf < 8; nf++) {
            O[nf][0] = OSM[il0 * 68 + nf * 8 + 2 * tig];
            O[nf][1] = OSM[il0 * 68 + nf * 8 + 2 * tig + 1];
            O[nf][2] = OSM[(il0 + 8) * 68 + nf * 8 + 2 * tig];
            O[nf][3] = OSM[(il0 + 8) * 68 + nf * 8 + 2 * tig + 1];
        }
    } else {
        m_r[0] = m_r[1] = -3.0e38f;
        l_r[0] = l_r[1] = 0.f;
    }
    __syncthreads();

    for (int kt = 0; kt <= qt; kt++) {
        const int cur = kt & 1;
        asm volatile("bar.sync %0, 128;" :: "r"(1 + g) : "memory");
        if (kt + 1 <= qt) {
            const int st = cur ^ 1;
            const uint4* ks = ktileb + (size_t)(kt + 1) * 256;
            #pragma unroll
            for (int it = 0; it < 2; it++)
                cpa16(ks_su[st] + (gtid + it * 128) * 16, ks + gtid + it * 128);
            const uint4* vs = vtileb + (size_t)(kt + 1) * 256;
            #pragma unroll
            for (int it = 0; it < 2; it++)
                cpa16(vs_su[st] + (gtid + it * 128) * 16, vs + gtid + it * 128);
            const float* bsrc = relrow + (size_t)(kt + 1) * 64 + g * 32;
            #pragma unroll
            for (int it = 0; it < 4; it++) {
                int c = gtid + it * 128;
                int r = c >> 3, c4 = c & 7;
                cpa16(bs_su[st] + (r * 36 + c4 * 4) * 4, bsrc + (size_t)r * NSEQ + c4 * 4);
            }
        }
        asm volatile("cp.async.commit_group;" ::: "memory");
        asm volatile("cp.async.wait_group 1;" ::: "memory");
        asm volatile("bar.sync %0, 128;" :: "r"(1 + g) : "memory");

        const uint32_t* KSc = smu + 4096 + g * 1024 + cur * STB;
        const uint32_t* VSc = smu + 6144 + g * 1024 + cur * STB;
        const float*    BSc = (const float*)(smu + 8192 + g * 2304 + cur * STB);

        float S[4][4] = {};
        #pragma unroll
        for (int kf = 0; kf < 4; kf++) {
            const uint32_t* qp = &QF[((mw * 4 + kf) * 32 + lane) * 8];
            uint4 ah = *(const uint4*)qp;
            uint4 al = *(const uint4*)(qp + 4);
            #pragma unroll
            for (int nf = 0; nf < 4; nf++) {
                uint2 kb = *(const uint2*)&KSc[((nf * 4 + kf) * 32 + lane) * 2];
                mma16(S[nf], ah.x, ah.y, ah.z, ah.w, kb.x, kb.y);
                mma16(S[nf], al.x, al.y, al.z, al.w, kb.x, kb.y);
            }
        }

        uint32_t ph[4][2];
        #pragma unroll
        for (int rr = 0; rr < 2; rr++) {
            int il = il0 + rr * 8;
            float mx = -3.0e38f;
            #pragma unroll
            for (int nf = 0; nf < 4; nf++) {
                int colb = g * 32 + nf * 8 + 2 * tig;
                float2 b2 = *(const float2*)&BSc[il * 36 + nf * 8 + 2 * tig];
                float s0 = fmaf(S[nf][2 * rr], scaleL2, b2.x * L2E);
                float s1 = fmaf(S[nf][2 * rr + 1], scaleL2, b2.y * L2E);
                if (kt == qt) {
                    if (colb     > il) s0 = -3.0e38f;
                    if (colb + 1 > il) s1 = -3.0e38f;
                }
                S[nf][2 * rr] = s0; S[nf][2 * rr + 1] = s1;
                mx = fmaxf(mx, fmaxf(s0, s1));
            }
            mx = fmaxf(mx, __shfl_xor_sync(0xffffffffu, mx, 1));
            mx = fmaxf(mx, __shfl_xor_sync(0xffffffffu, mx, 2));
            float mnew = fmaxf(m_r[rr], mx);
            float f = ex2(m_r[rr] - mnew);
            m_r[rr] = mnew;
            float ls = 0.f;
            #pragma unroll
            for (int nf = 0; nf < 4; nf++) {
                float p0 = ex2(S[nf][2 * rr] - mnew);
                float p1 = ex2(S[nf][2 * rr + 1] - mnew);
                ls += p0 + p1;
                ph[nf][rr] = h2bits(__floats2half2_rn(p0, p1));
            }
            #pragma unroll
            for (int nf = 0; nf < 8; nf++) {
                O[nf][2 * rr]     *= f;
                O[nf][2 * rr + 1] *= f;
            }
            ls += __shfl_xor_sync(0xffffffffu, ls, 1);
            ls += __shfl_xor_sync(0xffffffffu, ls, 2);
            l_r[rr] = l_r[rr] * f + ls;
        }

        #pragma unroll
        for (int kfl = 0; kfl < 2; kfl++) {
            uint32_t a0 = ph[2 * kfl][0], a1 = ph[2 * kfl][1];
            uint32_t a2 = ph[2 * kfl + 1][0], a3 = ph[2 * kfl + 1][1];
            #pragma unroll
            for (int nfd = 0; nfd < 8; nfd++) {
                uint2 vb = *(const uint2*)&VSc[((kfl * 8 + nfd) * 32 + lane) * 2];
                mma16(O[nfd], a0, a1, a2, a3, vb.x, vb.y);
            }
        }
    }

    asm volatile("cp.async.wait_group 0;" ::: "memory");
    __syncthreads();
    if (ng == 1) {
        #pragma unroll
        for (int rr = 0; rr < 2; rr++) {
            int il = il0 + rr * 8;
            RM[64 + il] = m_r[rr];
            RL[64 + il] = l_r[rr];
            #pragma unroll
            for (int nf = 0; nf < 8; nf++) {
                float2 v = make_float2(O[nf][2 * rr], O[nf][2 * rr + 1]);
                *(float2*)&OMG[il * 72 + nf * 8 + 2 * tig] = v;
            }
        }
    }
    __syncthreads();
    if (ng == 0) {
        #pragma unroll
        for (int rr = 0; rr < 2; rr++) {
            int il = il0 + rr * 8;
            float m1 = RM[64 + il], l1 = RL[64 + il];
            float m = fmaxf(m_r[rr], m1);
            float f0 = ex2(m_r[rr] - m), f1 = ex2(m1 - m);
            float inv = 1.0f / (l_r[rr] * f0 + l1 * f1);
            #pragma unroll
            for (int nf = 0; nf < 8; nf++) {
                float2 o1 = *(const float2*)&OMG[il * 72 + nf * 8 + 2 * tig];
                O[nf][2 * rr]     = (O[nf][2 * rr]     * f0 + o1.x * f1) * inv;
                O[nf][2 * rr + 1] = (O[nf][2 * rr + 1] * f0 + o1.y * f1) * inv;
            }
        }
        int band = bb * 128 + qt * 4 + mw;
        #pragma unroll
        for (int kf = 0; kf < 4; kf++) {
            uint32_t l0, l1, l2, l3;
            uint32_t h0 = split_pair_h(O[2 * kf][0],     O[2 * kf][1],     l0);
            uint32_t h1 = split_pair_h(O[2 * kf][2],     O[2 * kf][3],     l1);
            uint32_t h2 = split_pair_h(O[2 * kf + 1][0], O[2 * kf + 1][1], l2);
            uint32_t h3 = split_pair_h(O[2 * kf + 1][2], O[2 * kf + 1][3], l3);
            size_t slot = ((size_t)band * 32 + (hh * 4 + kf)) * 32 + lane;
            *(uint4*)&g_af[slot * 8]     = make_uint4(h0, h1, h2, h3);
            *(uint4*)&g_af[slot * 8 + 4] = make_uint4(l0, l1, l2, l3);
        }
    }
}

// ---------------------------------------------------------------------------
extern "C" void kernel_launch(void* const* d_in, const int* in_sizes, int n_in,
                              void* d_out, int out_size)
{
    const float* x      = (const float*)d_in[0];
    const float* memkv  = (const float*)d_in[1];
    const float* rel    = (const float*)d_in[3];
    const float* Wq     = (const float*)d_in[4];
    const float* Wkv    = (const float*)d_in[5];
    const float* Wout   = (const float*)d_in[6];
    const float* scalep = (const float*)d_in[7];
    float* out = (float*)d_out;

    const int SMEM = (4096 + 2 * STB + 256) * (int)sizeof(uint32_t);  // 87040 B
    cudaFuncSetAttribute(attn_mma, cudaFuncAttributeMaxDynamicSharedMemorySize, SMEM);

    const int M = BATCH * NSEQ;
    pack_in<<<1792, 256>>>(x, Wq, Wkv, Wout);
    gemm_qkv<<<dim3(6, M / 64), 256>>>();
    attn_mma<<<dim3(BATCH, HEADS, NT), 256, SMEM>>>(memkv, rel, scalep);
    gemm_out<<<dim3(4, M / 64), 256>>>(out);
}

// round 17
// speedup vs baseline: 1.2827x; 1.0083x over previous
#include <cuda_runtime.h>
#include <cuda_fp16.h>
#include <math.h>
#include <stdint.h>

#define NSEQ 2048
#define BATCH 2
#define HEADS 8
#define DH 64
#define KRET 32
#define DIM 512
#define NT 32
#define L2E 1.4426950408889634f

__device__ float g_q[(size_t)BATCH * HEADS * NSEQ * DH];
__device__ uint2 g_kf[(size_t)BATCH * NT * 1024];
__device__ uint2 g_vf[(size_t)BATCH * NT * 1024];
__device__ uint32_t g_xf[(size_t)256 * 32 * 32 * 8];
__device__ uint32_t g_af[(size_t)256 * 32 * 32 * 8];
__device__ uint32_t g_wqf[(size_t)64 * 32 * 32 * 4];
__device__ uint32_t g_wkvf[(size_t)16 * 32 * 32 * 4];
__device__ uint32_t g_woutf[(size_t)64 * 32 * 32 * 2];
// split attention partials
__device__ float g_co[(size_t)BATCH * HEADS * NSEQ * DH];
__device__ float g_mo[(size_t)BATCH * HEADS * NSEQ * DH];
__device__ float g_cm[(size_t)BATCH * HEADS * NSEQ];
__device__ float g_cl[(size_t)BATCH * HEADS * NSEQ];
__device__ float g_mm[(size_t)BATCH * HEADS * NSEQ];
__device__ float g_ml[(size_t)BATCH * HEADS * NSEQ];

__device__ __forceinline__ void mma16(float* d, uint32_t a0, uint32_t a1, uint32_t a2,
                                      uint32_t a3, uint32_t b0, uint32_t b1) {
    asm volatile("mma.sync.aligned.m16n8k16.row.col.f32.f16.f16.f32 "
        "{%0,%1,%2,%3}, {%4,%5,%6,%7}, {%8,%9}, {%0,%1,%2,%3};"
        : "+f"(d[0]), "+f"(d[1]), "+f"(d[2]), "+f"(d[3])
        : "r"(a0), "r"(a1), "r"(a2), "r"(a3), "r"(b0), "r"(b1));
}
__device__ __forceinline__ float ex2(float x) {
    float r; asm("ex2.approx.f32 %0, %1;" : "=f"(r) : "f"(x)); return r;
}
__device__ __forceinline__ uint32_t h2bits(__half2 h) {
    uint32_t u; *(__half2*)&u = h; return u;
}
__device__ __forceinline__ uint32_t split_pair_h(float a, float b, uint32_t& lo) {
    __half ha = __float2half_rn(a), hb = __float2half_rn(b);
    float ra = a - __half2float(ha), rb = b - __half2float(hb);
    lo = h2bits(__floats2half2_rn(ra, rb));
    return h2bits(__halves2half2(ha, hb));
}
__device__ __forceinline__ uint32_t s2u(const void* p) {
    return (uint32_t)__cvta_generic_to_shared(p);
}
__device__ __forceinline__ void cpa16(uint32_t s, const void* g) {
    asm volatile("cp.async.cg.shared.global [%0], [%1], 16;" :: "r"(s), "l"(g) : "memory");
}

// ---------------------------------------------------------------------------
__global__ __launch_bounds__(256) void pack_in(const float* __restrict__ x,
                                               const float* __restrict__ Wq,
                                               const float* __restrict__ Wkv,
                                               const float* __restrict__ Wout)
{
    int bx = blockIdx.x;
    if (bx < 1024) {
        int s = bx * 256 + threadIdx.x;
        int band = s >> 10, rem = s & 1023;
        int kfg = rem >> 5, ln = rem & 31;
        int gid = ln >> 2, tig = ln & 3;
        const float* base = x + (size_t)(band * 16 + gid) * DIM + kfg * 16 + 2 * tig;
        float2 x00 = *(const float2*)base;
        float2 x10 = *(const float2*)(base + 8 * DIM);
        float2 x01 = *(const float2*)(base + 8);
        float2 x11 = *(const float2*)(base + 8 * DIM + 8);
        uint32_t l0, l1, l2, l3;
        uint32_t h0 = split_pair_h(x00.x, x00.y, l0);
        uint32_t h1 = split_pair_h(x10.x, x10.y, l1);
        uint32_t h2 = split_pair_h(x01.x, x01.y, l2);
        uint32_t h3 = split_pair_h(x11.x, x11.y, l3);
        *(uint4*)&g_xf[(size_t)s * 8]     = make_uint4(h0, h1, h2, h3);
        *(uint4*)&g_xf[(size_t)s * 8 + 4] = make_uint4(l0, l1, l2, l3);
    } else {
        int sel = (bx - 1024) >> 8;
        const float* W = sel == 0 ? Wq : (sel == 1 ? Wkv : Wout);
        int N = (sel == 1) ? 128 : 512;
        int s = ((bx - 1024) & 255) * 256 + threadIdx.x;
        if (s >= (N / 8) * 1024) return;
        int nfg = s >> 10, rem = s & 1023;
        int kfg = rem >> 5, ln = rem & 31;
        int gid = ln >> 2, tig = ln & 3;
        int n = nfg * 8 + gid, k0 = kfg * 16 + 2 * tig;
        uint32_t bl0, bl1;
        uint32_t bh0 = split_pair_h(W[(size_t)k0 * N + n], W[(size_t)(k0 + 1) * N + n], bl0);
        uint32_t bh1 = split_pair_h(W[(size_t)(k0 + 8) * N + n], W[(size_t)(k0 + 9) * N + n], bl1);
        if (sel == 2) {
            *(uint2*)&g_woutf[(size_t)s * 2] = make_uint2(bh0, bh1);
        } else {
            uint32_t* out = sel == 0 ? g_wqf : g_wkvf;
            *(uint4*)&out[(size_t)s * 4] = make_uint4(bh0, bh1, bl0, bl1);
        }
    }
}

// ---------------------------------------------------------------------------
template <int NF, int SPLITB>
__device__ __forceinline__ void gemm_core_t(const uint32_t* __restrict__ APK,
                                            const uint32_t* __restrict__ BPK,
                                            int band0, int nf0, int KFG,
                                            uint32_t* AF, uint32_t* BF,
                                            float S[][4])
{
    const int tid = threadIdx.x, lane = tid & 31, w = tid >> 5;
    const int mw = w & 3, nh = w >> 2;
    const int nslab = KFG >> 1;
    const int BSTG = NF * (SPLITB ? 256 : 128);
    const int BITER = SPLITB ? NF / 4 : NF / 8;
    const uint32_t a_su[2] = {s2u(AF), s2u(AF + 2048)};
    const uint32_t b_su[2] = {s2u(BF), s2u(BF + BSTG)};

    #pragma unroll
    for (int r = 0; r < NF / 2; r++)
        #pragma unroll
        for (int c = 0; c < 4; c++) S[r][c] = 0.f;

    #pragma unroll
    for (int it = 0; it < 2; it++) {
        int idx = tid + it * 256;
        int kf2 = idx >> 8, mb = (idx >> 6) & 3, ln = (idx >> 1) & 31, hf = idx & 1;
        cpa16(a_su[0] + (((kf2 * 4 + mb) * 32 + ln) * 8 + hf * 4) * 4,
              APK + ((size_t)((band0 + mb) * KFG + kf2) * 32 + ln) * 8 + hf * 4);
    }
    #pragma unroll
    for (int it = 0; it < BITER; it++) {
        int idx = tid + it * 256;
        if (SPLITB) {
            int kf2 = idx / (32 * NF), nf = (idx >> 5) % NF, lnb = idx & 31;
            cpa16(b_su[0] + ((kf2 * NF + nf) * 32 + lnb) * 16,
                  BPK + ((size_t)((nf0 + nf) * KFG + kf2) * 32 + lnb) * 4);
        } else {
            int kf2 = idx / (NF * 16), rem = idx % (NF * 16);
            int nf = rem >> 4, cq = rem & 15;
            cpa16(b_su[0] + ((kf2 * NF + nf) * 64 + cq * 4) * 4,
                  BPK + ((size_t)(nf0 + nf) * KFG + kf2) * 64 + cq * 4);
        }
    }
    asm volatile("cp.async.commit_group;" ::: "memory");

    for (int ks = 0; ks < nslab; ks++) {
        const int cur = ks & 1;
        __syncthreads();
        if (ks + 1 < nslab) {
            const int st = cur ^ 1;
            #pragma unroll
            for (int it = 0; it < 2; it++) {
                int idx = tid + it * 256;
                int kf2 = idx >> 8, mb = (idx >> 6) & 3, ln = (idx >> 1) & 31, hf = idx & 1;
                int kfg = (ks + 1) * 2 + kf2;
                cpa16(a_su[st] + (((kf2 * 4 + mb) * 32 + ln) * 8 + hf * 4) * 4,
                      APK + ((size_t)((band0 + mb) * KFG + kfg) * 32 + ln) * 8 + hf * 4);
            }
            #pragma unroll
            for (int it = 0; it < BITER; it++) {
                int idx = tid + it * 256;
                if (SPLITB) {
                    int kf2 = idx / (32 * NF), nf = (idx >> 5) % NF, lnb = idx & 31;
                    int kfg = (ks + 1) * 2 + kf2;
                    cpa16(b_su[st] + ((kf2 * NF + nf) * 32 + lnb) * 16,
                          BPK + ((size_t)((nf0 + nf) * KFG + kfg) * 32 + lnb) * 4);
                } else {
                    int kf2 = idx / (NF * 16), rem = idx % (NF * 16);
                    int nf = rem >> 4, cq = rem & 15;
                    int kfg = (ks + 1) * 2 + kf2;
                    cpa16(b_su[st] + ((kf2 * NF + nf) * 64 + cq * 4) * 4,
                          BPK + ((size_t)(nf0 + nf) * KFG + kfg) * 64 + cq * 4);
                }
            }
        }
        asm volatile("cp.async.commit_group;" ::: "memory");
        asm volatile("cp.async.wait_group 1;" ::: "memory");
        __syncthreads();

        uint32_t* AFc = AF + cur * 2048;
        uint32_t* BFc = BF + cur * BSTG;
        #pragma unroll
        for (int kf2 = 0; kf2 < 2; kf2++) {
            const uint32_t* ap = &AFc[((kf2 * 4 + mw) * 32 + lane) * 8];
            uint4 ah = *(const uint4*)ap;
            uint4 al = *(const uint4*)(ap + 4);
            #pragma unroll
            for (int nf = 0; nf < NF / 2; nf++) {
                if (SPLITB) {
                    uint4 kb = *(const uint4*)&BFc[((kf2 * NF + nh * (NF / 2) + nf) * 32 + lane) * 4];
                    mma16(S[nf], ah.x, ah.y, ah.z, ah.w, kb.x, kb.y);
                    mma16(S[nf], al.x, al.y, al.z, al.w, kb.x, kb.y);
                    mma16(S[nf], ah.x, ah.y, ah.z, ah.w, kb.z, kb.w);
                } else {
                    uint2 kb = *(const uint2*)&BFc[((kf2 * NF + nh * (NF / 2) + nf) * 32 + lane) * 2];
                    mma16(S[nf], ah.x, ah.y, ah.z, ah.w, kb.x, kb.y);
                    mma16(S[nf], al.x, al.y, al.z, al.w, kb.x, kb.y);
                }
            }
        }
    }
}

// ---------------------------------------------------------------------------
__global__ __launch_bounds__(256) void gemm_qkv()
{
    __shared__ uint32_t AF[2 * 2048];
    __shared__ uint32_t BF[2 * 4096];
    float* vsm   = (float*)BF;
    float* ssbuf = (float*)AF;

    const int tid = threadIdx.x, lane = tid & 31, w = tid >> 5;
    const int mw = w & 3, nh = w >> 2;
    const int gid = lane >> 2, tig = lane & 3;
    const int r0 = blockIdx.y * 64;
    const int bx = blockIdx.x;

    float S[8][4];

    if (bx < 4) {
        gemm_core_t<16, 1>(g_xf, g_wqf, r0 >> 4, bx * 16, DIM >> 4, AF, BF, S);
        #pragma unroll
        for (int rr = 0; rr < 2; rr++) {
            float ss = 0.f;
            #pragma unroll
            for (int nf = 0; nf < 8; nf++)
                ss += S[nf][2 * rr] * S[nf][2 * rr] + S[nf][2 * rr + 1] * S[nf][2 * rr + 1];
            ss += __shfl_xor_sync(0xffffffffu, ss, 1);
            ss += __shfl_xor_sync(0xffffffffu, ss, 2);
            float inv = 1.0f / fmaxf(sqrtf(ss), 1e-12f);
            int row = r0 + mw * 16 + gid + rr * 8;
            int bb = row >> 11, t = row & 2047;
            size_t base = (((size_t)bb * HEADS + bx * 2 + nh) * NSEQ + t) * DH;
            #pragma unroll
            for (int nf = 0; nf < 8; nf++) {
                float2 v = make_float2(S[nf][2 * rr] * inv, S[nf][2 * rr + 1] * inv);
                *(float2*)&g_q[base + nf * 8 + 2 * tig] = v;
            }
        }
        return;
    }

    const bool is_k = (bx == 4);
    gemm_core_t<8, 1>(g_xf, g_wkvf, r0 >> 4, is_k ? 0 : 8, DIM >> 4, AF, BF, S);
    const int colw = nh * 32;
    const int bbr = r0 >> 11, ktr = (r0 & 2047) >> 6;
    const size_t obase = ((size_t)bbr * NT + ktr) * 1024;

    if (is_k) {
        __syncthreads();
        #pragma unroll
        for (int rr = 0; rr < 2; rr++) {
            float ss = 0.f;
            #pragma unroll
            for (int nf = 0; nf < 4; nf++)
                ss += S[nf][2 * rr] * S[nf][2 * rr] + S[nf][2 * rr + 1] * S[nf][2 * rr + 1];
            ss += __shfl_xor_sync(0xffffffffu, ss, 1);
            ss += __shfl_xor_sync(0xffffffffu, ss, 2);
            if (tig == 0) ssbuf[nh * 64 + mw * 16 + gid + rr * 8] = ss;
        }
        __syncthreads();
        #pragma unroll
        for (int rr = 0; rr < 2; rr++) {
            int rloc = mw * 16 + gid + rr * 8;
            float ss = ssbuf[rloc] + ssbuf[64 + rloc];
            float inv = 1.0f / fmaxf(sqrtf(ss), 1e-12f);
            int nfp = mw * 2 + rr;
            #pragma unroll
            for (int p = 0; p < 2; p++) {
                float a0 = S[2 * p][2 * rr] * inv,     a1 = S[2 * p][2 * rr + 1] * inv;
                float c0 = S[2 * p + 1][2 * rr] * inv, c1 = S[2 * p + 1][2 * rr + 1] * inv;
                uint32_t bh0 = h2bits(__floats2half2_rn(a0, a1));
                uint32_t bh1 = h2bits(__floats2half2_rn(c0, c1));
                int kfp = nh * 2 + p;
                g_kf[obase + (nfp * 4 + kfp) * 32 + lane] = make_uint2(bh0, bh1);
            }
        }
    } else {
        __syncthreads();
        #pragma unroll
        for (int rr = 0; rr < 2; rr++) {
            int rloc = mw * 16 + gid + rr * 8;
            #pragma unroll
            for (int nf = 0; nf < 4; nf++) {
                vsm[rloc * 68 + colw + nf * 8 + 2 * tig]     = S[nf][2 * rr];
                vsm[rloc * 68 + colw + nf * 8 + 2 * tig + 1] = S[nf][2 * rr + 1];
            }
        }
        __syncthreads();
        #pragma unroll
        for (int it = 0; it < 4; it++) {
            int s = tid + it * 256;
            int kg = s >> 8, nfd = (s >> 5) & 7, ln = s & 31;
            int gd = ln >> 2, tg = ln & 3;
            int key0 = kg * 16 + 2 * tg, d = nfd * 8 + gd;
            uint32_t b0 = h2bits(__floats2half2_rn(vsm[key0 * 68 + d], vsm[(key0 + 1) * 68 + d]));
            uint32_t b1 = h2bits(__floats2half2_rn(vsm[(key0 + 8) * 68 + d], vsm[(key0 + 9) * 68 + d]));
            g_vf[obase + s] = make_uint2(b0, b1);
        }
    }
}

// ---------------------------------------------------------------------------
__global__ __launch_bounds__(256) void gemm_out(float* __restrict__ C)
{
    __shared__ uint32_t AF[2 * 2048];
    __shared__ uint32_t BF[2 * 2048];

    const int tid = threadIdx.x, lane = tid & 31, w = tid >> 5;
    const int mw = w & 3, nh = w >> 2;
    const int gid = lane >> 2, tig = lane & 3;
    const int r0 = blockIdx.y * 64, c0 = blockIdx.x * 128;

    float S[8][4];
    gemm_core_t<16, 0>(g_af, g_woutf, r0 >> 4, c0 >> 3, DIM >> 4, AF, BF, S);
    const int row0 = r0 + mw * 16 + gid;
    const int colw = nh * 64;

    #pragma unroll
    for (int rr = 0; rr < 2; rr++)
        #pragma unroll
        for (int nf = 0; nf < 8; nf++) {
            float2 v = make_float2(S[nf][2 * rr], S[nf][2 * rr + 1]);
            *(float2*)&C[(size_t)(row0 + rr * 8) * DIM + c0 + colw + nf * 8 + 2 * tig] = v;
        }
}

// ---------------------------------------------------------------------------
// Heterogeneous attention: grid (BATCH, HEADS, 2*NT). Odd z = mem block
// (pure memkv stream, SIMT fp32, writes unnormalized O_m/m/l). Even z =
// causal block (R14 loop, no prologue; writes unnormalized O_c/m/l).
// ---------------------------------------------------------------------------
#define STB 8704
__global__ __launch_bounds__(256, 2) void attn_fused(const float* __restrict__ memkv,
                                                     const float* __restrict__ rel,
                                                     const float* __restrict__ scale_param)
{
    extern __shared__ uint32_t smu[];
    const int bb = blockIdx.x, hh = blockIdx.y;
    const int zz = blockIdx.z;
    const bool is_mem = (zz & 1);
    const int qt_raw = zz >> 1;
    const int tid = threadIdx.x;
    const float scaleL2 = expf(scale_param[hh]) * L2E;

    if (is_mem) {
        // ================= MEM BLOCK: 64 queries x 32 keys =================
        float* PMEM = (float*)smu;   // 64 x 36
        const int qt = qt_raw;
        const int qi = tid >> 2, qtr = tid & 3;
        const size_t rb = ((size_t)bb * HEADS + hh) * NSEQ + (size_t)qt * 64 + qi;
        const float* qrow = g_q + rb * DH + qtr * 16;
        float4 q4[4];
        #pragma unroll
        for (int u = 0; u < 4; u++) q4[u] = *(const float4*)&qrow[u * 4];
        const float* mk = memkv + (rb * KRET) * 128 + qtr * 16;

        float sj[8];
        #pragma unroll 4
        for (int j = 0; j < 32; j++) {
            const float* kp = mk + (size_t)j * 128;
            float p = 0.f;
            #pragma unroll
            for (int u = 0; u < 4; u++) {
                float4 k4 = __ldg((const float4*)&kp[u * 4]);
                p += q4[u].x * k4.x + q4[u].y * k4.y + q4[u].z * k4.z + q4[u].w * k4.w;
            }
            p += __shfl_xor_sync(0xffffffffu, p, 1);
            p += __shfl_xor_sync(0xffffffffu, p, 2);
            if ((j & 3) == qtr) sj[j >> 2] = p * scaleL2;
        }
        float mx = -3.0e38f;
        #pragma unroll
        for (int u = 0; u < 8; u++) mx = fmaxf(mx, sj[u]);
        mx = fmaxf(mx, __shfl_xor_sync(0xffffffffu, mx, 1));
        mx = fmaxf(mx, __shfl_xor_sync(0xffffffffu, mx, 2));
        float ls = 0.f;
        #pragma unroll
        for (int u = 0; u < 8; u++) {
            float pe = ex2(sj[u] - mx);
            ls += pe;
            PMEM[qi * 36 + u * 4 + qtr] = pe;
        }
        ls += __shfl_xor_sync(0xffffffffu, ls, 1);
        ls += __shfl_xor_sync(0xffffffffu, ls, 2);
        if (!qtr) { g_mm[rb] = mx; g_ml[rb] = ls; }
        __syncwarp();

        const float* vb = memkv + (rb * KRET) * 128 + 64 + qtr * 16;
        float4 acc[4] = {};
        #pragma unroll 2
        for (int j = 0; j < 32; j++) {
            float p = PMEM[qi * 36 + j];
            #pragma unroll
            for (int u = 0; u < 4; u++) {
                float4 v4 = __ldg((const float4*)&vb[(size_t)j * 128 + u * 4]);
                acc[u].x += p * v4.x; acc[u].y += p * v4.y;
                acc[u].z += p * v4.z; acc[u].w += p * v4.w;
            }
        }
        float* dst = g_mo + rb * DH + qtr * 16;
        #pragma unroll
        for (int u = 0; u < 4; u++) *(float4*)&dst[u * 4] = acc[u];
        return;
    }

    // ================= CAUSAL BLOCK =================
    uint32_t* QF  = smu;
    float* OMG  = (float*)(smu + 4096);            // epilogue alias (stage0)
    float* RM   = (float*)(smu + 4096 + 2 * STB);
    float* RL   = RM + 128;

    const int qt = NT - 1 - qt_raw;
    const int lane = tid & 31, w = tid >> 5;
    const int mw = w & 3, ng = w >> 2;
    const int g = ng, gtid = tid & 127;
    const int gid = lane >> 2, tig = lane & 3;
    const int il0 = 16 * mw + gid;

    const uint32_t ks_su[2] = {s2u(smu + 4096 + g * 1024),
                               s2u(smu + 4096 + g * 1024 + STB)};
    const uint32_t vs_su[2] = {s2u(smu + 6144 + g * 1024),
                               s2u(smu + 6144 + g * 1024 + STB)};
    const uint32_t bs_su[2] = {s2u(smu + 8192 + g * 2304),
                               s2u(smu + 8192 + g * 2304 + STB)};
    const float* relrow = rel + ((size_t)hh * NSEQ + (size_t)qt * 64) * NSEQ;
    const uint4* ktileb = (const uint4*)(g_kf + (size_t)bb * NT * 1024 + g * 512);
    const uint4* vtileb = (const uint4*)(g_vf + (size_t)bb * NT * 1024 + g * 512);

    {
        #pragma unroll
        for (int it = 0; it < 2; it++)
            cpa16(ks_su[0] + (gtid + it * 128) * 16, ktileb + gtid + it * 128);
        #pragma unroll
        for (int it = 0; it < 2; it++)
            cpa16(vs_su[0] + (gtid + it * 128) * 16, vtileb + gtid + it * 128);
        const float* bsrc = relrow + g * 32;
        #pragma unroll
        for (int it = 0; it < 4; it++) {
            int c = gtid + it * 128;
            int r = c >> 3, c4 = c & 7;
            cpa16(bs_su[0] + (r * 36 + c4 * 4) * 4, bsrc + (size_t)r * NSEQ + c4 * 4);
        }
        asm volatile("cp.async.commit_group;" ::: "memory");
    }

    const float* qbase = g_q + (((size_t)bb * HEADS + hh) * NSEQ + (size_t)qt * 64) * DH;
    if (ng == 0) {
        #pragma unroll
        for (int kf = 0; kf < 4; kf++) {
            int d0 = kf * 16 + 2 * tig;
            float2 q00 = *(const float2*)&qbase[il0 * DH + d0];
            float2 q10 = *(const float2*)&qbase[(il0 + 8) * DH + d0];
            float2 q01 = *(const float2*)&qbase[il0 * DH + d0 + 8];
            float2 q11 = *(const float2*)&qbase[(il0 + 8) * DH + d0 + 8];
            uint32_t al0, al1, al2, al3;
            uint32_t ah0 = split_pair_h(q00.x, q00.y, al0);
            uint32_t ah1 = split_pair_h(q10.x, q10.y, al1);
            uint32_t ah2 = split_pair_h(q01.x, q01.y, al2);
            uint32_t ah3 = split_pair_h(q11.x, q11.y, al3);
            uint32_t* qp = &QF[((mw * 4 + kf) * 32 + lane) * 8];
            *(uint4*)qp       = make_uint4(ah0, ah1, ah2, ah3);
            *(uint4*)(qp + 4) = make_uint4(al0, al1, al2, al3);
        }
    }
    __syncthreads();   // QF visible to all warps

    float O[8][4] = {}, m_r[2], l_r[2];
    m_r[0] = m_r[1] = -3.0e38f;
    l_r[0] = l_r[1] = 0.f;

    for (int kt = 0; kt <= qt; kt++) {
        const int cur = kt & 1;
        asm volatile("bar.sync %0, 128;" :: "r"(1 + g) : "memory");
        if (kt + 1 <= qt) {
            const int st = cur ^ 1;
            const uint4* ks = ktileb + (size_t)(kt + 1) * 256;
            #pragma unroll
            for (int it = 0; it < 2; it++)
                cpa16(ks_su[st] + (gtid + it * 128) * 16, ks + gtid + it * 128);
            const uint4* vs = vtileb + (size_t)(kt + 1) * 256;
            #pragma unroll
            for (int it = 0; it < 2; it++)
                cpa16(vs_su[st] + (gtid + it * 128) * 16, vs + gtid + it * 128);
            const float* bsrc = relrow + (size_t)(kt + 1) * 64 + g * 32;
            #pragma unroll
            for (int it = 0; it < 4; it++) {
                int c = gtid + it * 128;
                int r = c >> 3, c4 = c & 7;
                cpa16(bs_su[st] + (r * 36 + c4 * 4) * 4, bsrc + (size_t)r * NSEQ + c4 * 4);
            }
        }
        asm volatile("cp.async.commit_group;" ::: "memory");
        asm volatile("cp.async.wait_group 1;" ::: "memory");
        asm volatile("bar.sync %0, 128;" :: "r"(1 + g) : "memory");

        const uint32_t* KSc = smu + 4096 + g * 1024 + cur * STB;
        const uint32_t* VSc = smu + 6144 + g * 1024 + cur * STB;
        const float*    BSc = (const float*)(smu + 8192 + g * 2304 + cur * STB);

        float S[4][4] = {};
        #pragma unroll
        for (int kf = 0; kf < 4; kf++) {
            const uint32_t* qp = &QF[((mw * 4 + kf) * 32 + lane) * 8];
            uint4 ah = *(const uint4*)qp;
            uint4 al = *(const uint4*)(qp + 4);
            #pragma unroll
            for (int nf = 0; nf < 4; nf++) {
                uint2 kb = *(const uint2*)&KSc[((nf * 4 + kf) * 32 + lane) * 2];
                mma16(S[nf], ah.x, ah.y, ah.z, ah.w, kb.x, kb.y);
                mma16(S[nf], al.x, al.y, al.z, al.w, kb.x, kb.y);
            }
        }

        uint32_t ph[4][2];
        #pragma unroll
        for (int rr = 0; rr < 2; rr++) {
            int il = il0 + rr * 8;
            float mx = -3.0e38f;
            #pragma unroll
            for (int nf = 0; nf < 4; nf++) {
                int colb = g * 32 + nf * 8 + 2 * tig;
                float2 b2 = *(const float2*)&BSc[il * 36 + nf * 8 + 2 * tig];
                float s0 = fmaf(S[nf][2 * rr], scaleL2, b2.x * L2E);
                float s1 = fmaf(S[nf][2 * rr + 1], scaleL2, b2.y * L2E);
                if (kt == qt) {
                    if (colb     > il) s0 = -3.0e38f;
                    if (colb + 1 > il) s1 = -3.0e38f;
                }
                S[nf][2 * rr] = s0; S[nf][2 * rr + 1] = s1;
                mx = fmaxf(mx, fmaxf(s0, s1));
            }
            mx = fmaxf(mx, __shfl_xor_sync(0xffffffffu, mx, 1));
            mx = fmaxf(mx, __shfl_xor_sync(0xffffffffu, mx, 2));
            float mnew = fmaxf(m_r[rr], mx);
            float f = ex2(m_r[rr] - mnew);
            m_r[rr] = mnew;
            float ls = 0.f;
            #pragma unroll
            for (int nf = 0; nf < 4; nf++) {
                float p0 = ex2(S[nf][2 * rr] - mnew);
                float p1 = ex2(S[nf][2 * rr + 1] - mnew);
                ls += p0 + p1;
                ph[nf][rr] = h2bits(__floats2half2_rn(p0, p1));
            }
            #pragma unroll
            for (int nf = 0; nf < 8; nf++) {
                O[nf][2 * rr]     *= f;
                O[nf][2 * rr + 1] *= f;
            }
            ls += __shfl_xor_sync(0xffffffffu, ls, 1);
            ls += __shfl_xor_sync(0xffffffffu, ls, 2);
            l_r[rr] = l_r[rr] * f + ls;
        }

        #pragma unroll
        for (int kfl = 0; kfl < 2; kfl++) {
            uint32_t a0 = ph[2 * kfl][0], a1 = ph[2 * kfl][1];
            uint32_t a2 = ph[2 * kfl + 1][0], a3 = ph[2 * kfl + 1][1];
            #pragma unroll
            for (int nfd = 0; nfd < 8; nfd++) {
                uint2 vb = *(const uint2*)&VSc[((kfl * 8 + nfd) * 32 + lane) * 2];
                mma16(O[nfd], a0, a1, a2, a3, vb.x, vb.y);
            }
        }
    }

    // ---- merge ng pair, write unnormalized O_c + m/l ----
    asm volatile("cp.async.wait_group 0;" ::: "memory");
    __syncthreads();
    if (ng == 1) {
        #pragma unroll
        for (int rr = 0; rr < 2; rr++) {
            int il = il0 + rr * 8;
            RM[64 + il] = m_r[rr];
            RL[64 + il] = l_r[rr];
            #pragma unroll
            for (int nf = 0; nf < 8; nf++) {
                float2 v = make_float2(O[nf][2 * rr], O[nf][2 * rr + 1]);
                *(float2*)&OMG[il * 72 + nf * 8 + 2 * tig] = v;
            }
        }
    }
    __syncthreads();
    if (ng == 0) {
        #pragma unroll
        for (int rr = 0; rr < 2; rr++) {
            int il = il0 + rr * 8;
            float m1 = RM[64 + il], l1 = RL[64 + il];
            float m = fmaxf(m_r[rr], m1);
            float f0 = ex2(m_r[rr] - m), f1 = ex2(m1 - m);
            float lc = l_r[rr] * f0 + l1 * f1;
            size_t rb = ((size_t)bb * HEADS + hh) * NSEQ + (size_t)qt * 64 + il;
            if (tig == 0) { g_cm[rb] = m; g_cl[rb] = lc; }
            float* dst = g_co + rb * DH;
            #pragma unroll
            for (int nf = 0; nf < 8; nf++) {
                float2 o1 = *(const float2*)&OMG[il * 72 + nf * 8 + 2 * tig];
                float2 v = make_float2(O[nf][2 * rr] * f0 + o1.x * f1,
                                       O[nf][2 * rr + 1] * f0 + o1.y * f1);
                *(float2*)&dst[nf * 8 + 2 * tig] = v;
            }
        }
    }
}

// ---------------------------------------------------------------------------
// Merge causal + mem partials -> g_af fragments. Grid (BATCH, HEADS, NT),
// 128 threads (4 warps, warp mw handles rows mw*16..+15 in frag layout).
// ---------------------------------------------------------------------------
__global__ __launch_bounds__(128) void attn_merge()
{
    const int bb = blockIdx.x, hh = blockIdx.y, qt = blockIdx.z;
    const int tid = threadIdx.x, lane = tid & 31, mw = tid >> 5;
    const int gid = lane >> 2, tig = lane & 3;
    const int il0 = 16 * mw + gid;

    float O[8][4];
    #pragma unroll
    for (int rr = 0; rr < 2; rr++) {
        int il = il0 + rr * 8;
        size_t rb = ((size_t)bb * HEADS + hh) * NSEQ + (size_t)qt * 64 + il;
        float mc = g_cm[rb], lc = g_cl[rb];
        float mm = g_mm[rb], lm = g_ml[rb];
        float m = fmaxf(mc, mm);
        float fc = ex2(mc - m), fm = ex2(mm - m);
        float inv = 1.0f / (lc * fc + lm * fm);
        const float* co = g_co + rb * DH;
        const float* mo = g_mo + rb * DH;
        #pragma unroll
        for (int nf = 0; nf < 8; nf++) {
            float2 oc = *(const float2*)&co[nf * 8 + 2 * tig];
            float2 om = *(const float2*)&mo[nf * 8 + 2 * tig];
            O[nf][2 * rr]     = (oc.x * fc + om.x * fm) * inv;
            O[nf][2 * rr + 1] = (oc.y * fc + om.y * fm) * inv;
        }
    }

    int band = bb * 128 + qt * 4 + mw;
    #pragma unroll
    for (int kf = 0; kf < 4; kf++) {
        uint32_t l0, l1, l2, l3;
        uint32_t h0 = split_pair_h(O[2 * kf][0],     O[2 * kf][1],     l0);
        uint32_t h1 = split_pair_h(O[2 * kf][2],     O[2 * kf][3],     l1);
        uint32_t h2 = split_pair_h(O[2 * kf + 1][0], O[2 * kf + 1][1], l2);
        uint32_t h3 = split_pair_h(O[2 * kf + 1][2], O[2 * kf + 1][3], l3);
        size_t slot = ((size_t)band * 32 + (hh * 4 + kf)) * 32 + lane;
        *(uint4*)&g_af[slot * 8]     = make_uint4(h0, h1, h2, h3);
        *(uint4*)&g_af[slot * 8 + 4] = make_uint4(l0, l1, l2, l3);
    }
}

// ---------------------------------------------------------------------------
extern "C" void kernel_launch(void* const* d_in, const int* in_sizes, int n_in,
                              void* d_out, int out_size)
{
    const float* x      = (const float*)d_in[0];
    const float* memkv  = (const float*)d_in[1];
    const float* rel    = (const float*)d_in[3];
    const float* Wq     = (const float*)d_in[4];
    const float* Wkv    = (const float*)d_in[5];
    const float* Wout   = (const float*)d_in[6];
    const float* scalep = (const float*)d_in[7];
    float* out = (float*)d_out;

    const int SMEM = (4096 + 2 * STB + 256) * (int)sizeof(uint32_t);  // 87040 B
    cudaFuncSetAttribute(attn_fused, cudaFuncAttributeMaxDynamicSharedMemorySize, SMEM);

    const int M = BATCH * NSEQ;
    pack_in<<<1792, 256>>>(x, Wq, Wkv, Wout);
    gemm_qkv<<<dim3(6, M / 64), 256>>>();
    attn_fused<<<dim3(BATCH, HEADS, 2 * NT), 256, SMEM>>>(memkv, rel, scalep);
    attn_merge<<<dim3(BATCH, HEADS, NT), 128>>>();
    gemm_out<<<dim3(4, M / 64), 256>>>(out);
}